// round 1
// baseline (speedup 1.0000x reference)
#include <cuda_runtime.h>
#include <math.h>

#define NN    16384
#define EE    524288
#define BB    8
#define FIN   26
#define DD    128
#define HH    256
#define OUTD  64
#define NL    4
#define NRBF  16
#define KIN   272   // 2*DD + NRBF

// ---------------- scratch (device globals; no allocation allowed) ----------
__device__ float g_h[NN * DD];
__device__ float g_agg[NN * DD];
__device__ float g_ef[EE * NRBF];
__device__ float g_gsum[BB * DD];
__device__ float g_gcnt[BB];

__device__ __forceinline__ float silu_f(float x) {
    return x * (1.0f / (1.0f + __expf(-x)));
}

// ---------------- node embedding: (N,26) -> silu -> (N,128) ----------------
__global__ void __launch_bounds__(128) embed_k(
    const float* __restrict__ nf,
    const float* __restrict__ W1, const float* __restrict__ b1,
    const float* __restrict__ W2, const float* __restrict__ b2,
    float* __restrict__ h)
{
    __shared__ __align__(16) float s_in[16 * FIN];
    __shared__ __align__(16) float s_hid[16 * DD];
    const int tid = threadIdx.x;
    const int n0 = blockIdx.x * 16;

    for (int idx = tid; idx < 16 * FIN; idx += 128) {
        int e = idx / FIN, k = idx - e * FIN;
        s_in[idx] = nf[(n0 + e) * FIN + k];
    }
    __syncthreads();

    const int j = tid;  // 0..127
    float acc[16];
#pragma unroll
    for (int e = 0; e < 16; e++) acc[e] = 0.0f;
    for (int k = 0; k < FIN; k++) {
        float w = W1[k * DD + j];
#pragma unroll
        for (int e = 0; e < 16; e++) acc[e] = fmaf(s_in[e * FIN + k], w, acc[e]);
    }
    float bb1 = b1[j];
#pragma unroll
    for (int e = 0; e < 16; e++) s_hid[e * DD + j] = silu_f(acc[e] + bb1);
    __syncthreads();

    float acc2[16];
#pragma unroll
    for (int e = 0; e < 16; e++) acc2[e] = 0.0f;
    const float4* sh4 = (const float4*)s_hid;
    for (int k4 = 0; k4 < DD / 4; k4++) {
        const float* wp = &W2[(k4 * 4) * DD + j];
        float w0 = wp[0], w1 = wp[DD], w2 = wp[2 * DD], w3 = wp[3 * DD];
#pragma unroll
        for (int e = 0; e < 16; e++) {
            float4 a = sh4[e * (DD / 4) + k4];
            acc2[e] = fmaf(a.x, w0, acc2[e]);
            acc2[e] = fmaf(a.y, w1, acc2[e]);
            acc2[e] = fmaf(a.z, w2, acc2[e]);
            acc2[e] = fmaf(a.w, w3, acc2[e]);
        }
    }
    float bb2 = b2[j];
#pragma unroll
    for (int e = 0; e < 16; e++) h[(n0 + e) * DD + j] = acc2[e] + bb2;
}

// ---------------- per-edge RBF features (E,16) -----------------------------
__global__ void rbf_k(const float* __restrict__ pos, const int* __restrict__ EI,
                      float* __restrict__ ef)
{
    int e = blockIdx.x * blockDim.x + threadIdx.x;
    if (e >= EE) return;
    int s = EI[e];
    int d = EI[EE + e];
    float dx = pos[d * 3 + 0] - pos[s * 3 + 0];
    float dy = pos[d * 3 + 1] - pos[s * 3 + 1];
    float dz = pos[d * 3 + 2] - pos[s * 3 + 2];
    float dist = sqrtf(dx * dx + dy * dy + dz * dz + 1e-12f);
    float env = (dist < 10.0f)
                    ? 0.5f * (cosf(3.14159265358979323846f * dist * 0.1f) + 1.0f)
                    : 0.0f;
    const float inv2w2 = 1.0f / (2.0f * 0.625f * 0.625f);  // width = 10/16
#pragma unroll
    for (int k = 0; k < NRBF; k++) {
        float c = (10.0f / 15.0f) * (float)k;  // linspace(0,10,16)
        float t = dist - c;
        ef[e * NRBF + k] = __expf(-t * t * inv2w2) * env;
    }
}

// ---------------- message MLP + segment_sum scatter -------------------------
// 16 edges per block, 256 threads.
__global__ void __launch_bounds__(256) msg_k(
    const int* __restrict__ EI,
    const float* __restrict__ h, const float* __restrict__ ef,
    const float* __restrict__ W1, const float* __restrict__ b1,
    const float* __restrict__ W2, const float* __restrict__ b2,
    float* __restrict__ agg)
{
    __shared__ __align__(16) float s_in[16 * KIN];
    __shared__ __align__(16) float s_hid[16 * HH];
    __shared__ int s_dst[16];
    const int tid = threadIdx.x;
    const int e0 = blockIdx.x * 16;

    if (tid < 16) s_dst[tid] = EI[EE + e0 + tid];

    for (int idx = tid; idx < 16 * KIN; idx += 256) {
        int e = idx / KIN, k = idx - e * KIN;
        int ge = e0 + e;
        float v;
        if (k < DD)            v = h[EI[ge] * DD + k];
        else if (k < 2 * DD)   v = h[EI[EE + ge] * DD + (k - DD)];
        else                   v = ef[ge * NRBF + (k - 2 * DD)];
        s_in[idx] = v;
    }
    __syncthreads();

    // Stage 1: (16 x 272) @ (272 x 256) + bias -> silu -> s_hid
    {
        const int j = tid;  // hidden column 0..255
        float acc[16];
#pragma unroll
        for (int e = 0; e < 16; e++) acc[e] = 0.0f;
        const float4* si4 = (const float4*)s_in;
        for (int k4 = 0; k4 < KIN / 4; k4++) {
            const float* wp = &W1[(k4 * 4) * HH + j];
            float w0 = wp[0], w1 = wp[HH], w2 = wp[2 * HH], w3 = wp[3 * HH];
#pragma unroll
            for (int e = 0; e < 16; e++) {
                float4 a = si4[e * (KIN / 4) + k4];
                acc[e] = fmaf(a.x, w0, acc[e]);
                acc[e] = fmaf(a.y, w1, acc[e]);
                acc[e] = fmaf(a.z, w2, acc[e]);
                acc[e] = fmaf(a.w, w3, acc[e]);
            }
        }
        float bb = b1[j];
#pragma unroll
        for (int e = 0; e < 16; e++) s_hid[e * HH + j] = silu_f(acc[e] + bb);
    }
    __syncthreads();

    // Stage 2: (16 x 256) @ (256 x 128) + bias -> atomic scatter to agg[dst]
    {
        const int j = tid & (DD - 1);
        const int eb = (tid >> 7) * 8;
        float acc[8];
#pragma unroll
        for (int e = 0; e < 8; e++) acc[e] = 0.0f;
        const float4* sh4 = (const float4*)s_hid;
        for (int k4 = 0; k4 < HH / 4; k4++) {
            const float* wp = &W2[(k4 * 4) * DD + j];
            float w0 = wp[0], w1 = wp[DD], w2 = wp[2 * DD], w3 = wp[3 * DD];
#pragma unroll
            for (int e = 0; e < 8; e++) {
                float4 a = sh4[(eb + e) * (HH / 4) + k4];
                acc[e] = fmaf(a.x, w0, acc[e]);
                acc[e] = fmaf(a.y, w1, acc[e]);
                acc[e] = fmaf(a.z, w2, acc[e]);
                acc[e] = fmaf(a.w, w3, acc[e]);
            }
        }
        float bb = b2[j];
#pragma unroll
        for (int e = 0; e < 8; e++)
            atomicAdd(&agg[s_dst[eb + e] * DD + j], acc[e] + bb);
    }
}

// ---------------- node update MLP (residual, in-place) ----------------------
__global__ void __launch_bounds__(256) upd_k(
    float* __restrict__ h, const float* __restrict__ agg,
    const float* __restrict__ W1, const float* __restrict__ b1,
    const float* __restrict__ W2, const float* __restrict__ b2)
{
    __shared__ __align__(16) float s_in[16 * 2 * DD];
    __shared__ __align__(16) float s_hid[16 * HH];
    const int tid = threadIdx.x;
    const int n0 = blockIdx.x * 16;

    for (int idx = tid; idx < 16 * 2 * DD; idx += 256) {
        int e = idx >> 8, k = idx & 255;
        float v = (k < DD) ? h[(n0 + e) * DD + k] : agg[(n0 + e) * DD + (k - DD)];
        s_in[idx] = v;
    }
    __syncthreads();

    {
        const int j = tid;
        float acc[16];
#pragma unroll
        for (int e = 0; e < 16; e++) acc[e] = 0.0f;
        const float4* si4 = (const float4*)s_in;
        for (int k4 = 0; k4 < (2 * DD) / 4; k4++) {
            const float* wp = &W1[(k4 * 4) * HH + j];
            float w0 = wp[0], w1 = wp[HH], w2 = wp[2 * HH], w3 = wp[3 * HH];
#pragma unroll
            for (int e = 0; e < 16; e++) {
                float4 a = si4[e * ((2 * DD) / 4) + k4];
                acc[e] = fmaf(a.x, w0, acc[e]);
                acc[e] = fmaf(a.y, w1, acc[e]);
                acc[e] = fmaf(a.z, w2, acc[e]);
                acc[e] = fmaf(a.w, w3, acc[e]);
            }
        }
        float bb = b1[j];
#pragma unroll
        for (int e = 0; e < 16; e++) s_hid[e * HH + j] = silu_f(acc[e] + bb);
    }
    __syncthreads();

    {
        const int j = tid & (DD - 1);
        const int eb = (tid >> 7) * 8;
        float acc[8];
#pragma unroll
        for (int e = 0; e < 8; e++) acc[e] = 0.0f;
        const float4* sh4 = (const float4*)s_hid;
        for (int k4 = 0; k4 < HH / 4; k4++) {
            const float* wp = &W2[(k4 * 4) * DD + j];
            float w0 = wp[0], w1 = wp[DD], w2 = wp[2 * DD], w3 = wp[3 * DD];
#pragma unroll
            for (int e = 0; e < 8; e++) {
                float4 a = sh4[(eb + e) * (HH / 4) + k4];
                acc[e] = fmaf(a.x, w0, acc[e]);
                acc[e] = fmaf(a.y, w1, acc[e]);
                acc[e] = fmaf(a.z, w2, acc[e]);
                acc[e] = fmaf(a.w, w3, acc[e]);
            }
        }
        float bb = b2[j];
#pragma unroll
        for (int e = 0; e < 8; e++)
            h[(n0 + eb + e) * DD + j] += acc[e] + bb;
    }
}

// ---------------- per-graph counts ------------------------------------------
__global__ void cnt_k(const int* __restrict__ batch, float* __restrict__ cnt)
{
    int n = blockIdx.x * blockDim.x + threadIdx.x;
    if (n < NN) atomicAdd(&cnt[batch[n]], 1.0f);
}

// ---------------- per-graph feature sums (batch sorted -> run compression) --
__global__ void __launch_bounds__(128) gsum_k(
    const float* __restrict__ h, const int* __restrict__ batch,
    float* __restrict__ gsum)
{
    const int j = threadIdx.x;  // 0..127
    const int n0 = blockIdx.x * 32;
    int curb = batch[n0];
    float acc = 0.0f;
    for (int i = 0; i < 32; i++) {
        int n = n0 + i;
        int b = batch[n];
        if (b != curb) {
            atomicAdd(&gsum[curb * DD + j], acc);
            acc = 0.0f;
            curb = b;
        }
        acc += h[n * DD + j];
    }
    atomicAdd(&gsum[curb * DD + j], acc);
}

// ---------------- readout MLP (single block) --------------------------------
__global__ void __launch_bounds__(256) final_k(
    const float* __restrict__ gsum, const float* __restrict__ cnt,
    const float* __restrict__ W1, const float* __restrict__ b1,
    const float* __restrict__ W2, const float* __restrict__ b2,
    float* __restrict__ out)
{
    __shared__ float sg[BB * DD];
    __shared__ float sh[BB * HH];
    const int tid = threadIdx.x;

    for (int idx = tid; idx < BB * DD; idx += 256) {
        int b = idx >> 7;
        sg[idx] = gsum[idx] / fmaxf(cnt[b], 1.0f);
    }
    __syncthreads();

    {
        const int j = tid;  // 0..255
        float acc[BB];
#pragma unroll
        for (int b = 0; b < BB; b++) acc[b] = 0.0f;
        for (int k = 0; k < DD; k++) {
            float w = W1[k * HH + j];
#pragma unroll
            for (int b = 0; b < BB; b++) acc[b] = fmaf(sg[b * DD + k], w, acc[b]);
        }
        float bb = b1[j];
#pragma unroll
        for (int b = 0; b < BB; b++) sh[b * HH + j] = silu_f(acc[b] + bb);
    }
    __syncthreads();

    if (tid < OUTD) {
        const int j = tid;
        float acc[BB];
#pragma unroll
        for (int b = 0; b < BB; b++) acc[b] = 0.0f;
        for (int k = 0; k < HH; k++) {
            float w = W2[k * OUTD + j];
#pragma unroll
            for (int b = 0; b < BB; b++) acc[b] = fmaf(sh[b * HH + k], w, acc[b]);
        }
        float bb = b2[j];
#pragma unroll
        for (int b = 0; b < BB; b++) out[b * OUTD + j] = acc[b] + bb;
    }
}

// ---------------- launch -----------------------------------------------------
extern "C" void kernel_launch(void* const* d_in, const int* in_sizes, int n_in,
                              void* d_out, int out_size)
{
    const float* pos    = (const float*)d_in[0];
    const float* nf     = (const float*)d_in[1];
    const int*   EI     = (const int*)d_in[2];
    const int*   batch  = (const int*)d_in[3];
    const float* emb_W1 = (const float*)d_in[4];
    const float* emb_b1 = (const float*)d_in[5];
    const float* emb_W2 = (const float*)d_in[6];
    const float* emb_b2 = (const float*)d_in[7];
    const float* msg_W1 = (const float*)d_in[8];
    const float* msg_b1 = (const float*)d_in[9];
    const float* msg_W2 = (const float*)d_in[10];
    const float* msg_b2 = (const float*)d_in[11];
    const float* upd_W1 = (const float*)d_in[12];
    const float* upd_b1 = (const float*)d_in[13];
    const float* upd_W2 = (const float*)d_in[14];
    const float* upd_b2 = (const float*)d_in[15];
    const float* r_W1   = (const float*)d_in[16];
    const float* r_b1   = (const float*)d_in[17];
    const float* r_W2   = (const float*)d_in[18];
    const float* r_b2   = (const float*)d_in[19];
    float* out = (float*)d_out;

    void *p_h, *p_agg, *p_ef, *p_gsum, *p_gcnt;
    cudaGetSymbolAddress(&p_h, g_h);
    cudaGetSymbolAddress(&p_agg, g_agg);
    cudaGetSymbolAddress(&p_ef, g_ef);
    cudaGetSymbolAddress(&p_gsum, g_gsum);
    cudaGetSymbolAddress(&p_gcnt, g_gcnt);
    float* h    = (float*)p_h;
    float* agg  = (float*)p_agg;
    float* ef   = (float*)p_ef;
    float* gsum = (float*)p_gsum;
    float* gcnt = (float*)p_gcnt;

    embed_k<<<NN / 16, 128>>>(nf, emb_W1, emb_b1, emb_W2, emb_b2, h);
    rbf_k<<<EE / 256, 256>>>(pos, EI, ef);

    for (int l = 0; l < NL; l++) {
        cudaMemsetAsync(agg, 0, (size_t)NN * DD * sizeof(float), 0);
        msg_k<<<EE / 16, 256>>>(EI, h, ef,
                                msg_W1 + (size_t)l * KIN * HH,
                                msg_b1 + (size_t)l * HH,
                                msg_W2 + (size_t)l * HH * DD,
                                msg_b2 + (size_t)l * DD,
                                agg);
        upd_k<<<NN / 16, 256>>>(h, agg,
                                upd_W1 + (size_t)l * 2 * DD * HH,
                                upd_b1 + (size_t)l * HH,
                                upd_W2 + (size_t)l * HH * DD,
                                upd_b2 + (size_t)l * DD);
    }

    cudaMemsetAsync(gsum, 0, (size_t)BB * DD * sizeof(float), 0);
    cudaMemsetAsync(gcnt, 0, (size_t)BB * sizeof(float), 0);
    cnt_k<<<NN / 256, 256>>>(batch, gcnt);
    gsum_k<<<NN / 32, 128>>>(h, batch, gsum);
    final_k<<<1, 256>>>(gsum, gcnt, r_W1, r_b1, r_W2, r_b2, out);
}

// round 3
// speedup vs baseline: 3.4353x; 3.4353x over previous
#include <cuda_runtime.h>
#include <math.h>
#include <stdint.h>

#define NN    16384
#define EE    524288
#define BB    8
#define FIN   26
#define DD    128
#define HH    256
#define OUTD  64
#define NL    4
#define NRBF  16
#define KIN   272          // 2*DD + NRBF
#define KC1   36           // GEMM1 k-chunks of 8 (K padded to 288)
#define KC2   32           // GEMM2 k-chunks of 8 (K = 256)

// ---------------- scratch (device globals; no allocation allowed) ----------
__device__ float g_h[NN * DD];
__device__ float g_agg[NN * DD];
__device__ float g_ef[EE * NRBF];
__device__ float g_gsum[BB * DD];
__device__ float g_gcnt[BB];
// W1 in B-fragment layout: [l][kc=36][npair=16][t=32][i=4]  (tf32)
__device__ float g_W1f[NL * KC1 * 16 * 32 * 4];
// W2 in B-fragment layout: [l][kc=32][npair=8][t=32][i=4]   (tf32)
__device__ float g_W2f[NL * KC2 * 8 * 32 * 4];

__device__ __forceinline__ float silu_f(float x) {
    return x * (1.0f / (1.0f + __expf(-x)));
}
__device__ __forceinline__ float to_tf32(float x) {
    uint32_t u;
    asm volatile("cvt.rna.tf32.f32 %0, %1;" : "=r"(u) : "f"(x));
    return __uint_as_float(u);
}

// m16n8k8 tf32 MMA (baseline PTX, valid on compute_103)
__device__ __forceinline__ void mma8(float* c, uint4 a, uint32_t b0, uint32_t b1) {
    asm volatile(
        "mma.sync.aligned.m16n8k8.row.col.f32.tf32.tf32.f32 "
        "{%0,%1,%2,%3}, {%4,%5,%6,%7}, {%8,%9}, {%0,%1,%2,%3};"
        : "+f"(c[0]), "+f"(c[1]), "+f"(c[2]), "+f"(c[3])
        : "r"(a.x), "r"(a.y), "r"(a.z), "r"(a.w), "r"(b0), "r"(b1));
}

// ---------------- weight prep: fragment layout, tf32 ------------------------
// B-frag for m16n8k8: b0 -> (k = t%4,     n = t/4)
//                     b1 -> (k = t%4 + 4, n = t/4)
// packed pairs of n-frags: [kc][npair][t][i]: i=0,1 -> frag 2p (b0,b1); i=2,3 -> frag 2p+1
__global__ void prep1_k(const float* __restrict__ W1, float* __restrict__ W1f) {
    int idx = blockIdx.x * 256 + threadIdx.x;
    const int PER = KC1 * 16 * 32 * 4;
    if (idx >= NL * PER) return;
    int l = idx / PER, r = idx - l * PER;
    int kc = r / 2048;           r -= kc * 2048;
    int np = r / 128;            r -= np * 128;
    int t = r / 4, i = r & 3;
    int k = kc * 8 + (t & 3) + 4 * (i & 1);
    int n = (np * 2 + (i >> 1)) * 8 + (t >> 2);
    W1f[idx] = (k < KIN) ? to_tf32(W1[((size_t)l * KIN + k) * HH + n]) : 0.0f;
}
__global__ void prep2_k(const float* __restrict__ W2, float* __restrict__ W2f) {
    int idx = blockIdx.x * 256 + threadIdx.x;
    const int PER = KC2 * 8 * 32 * 4;
    if (idx >= NL * PER) return;
    int l = idx / PER, r = idx - l * PER;
    int kc = r / 1024;           r -= kc * 1024;
    int np = r / 128;            r -= np * 128;
    int t = r / 4, i = r & 3;
    int k = kc * 8 + (t & 3) + 4 * (i & 1);
    int n = (np * 2 + (i >> 1)) * 8 + (t >> 2);
    W2f[idx] = to_tf32(W2[((size_t)l * HH + k) * DD + n]);
}

// ---------------- node embedding: (N,26) -> silu -> (N,128) ----------------
__global__ void __launch_bounds__(128) embed_k(
    const float* __restrict__ nf,
    const float* __restrict__ W1, const float* __restrict__ b1,
    const float* __restrict__ W2, const float* __restrict__ b2,
    float* __restrict__ h)
{
    __shared__ __align__(16) float s_in[16 * FIN];
    __shared__ __align__(16) float s_hid[16 * DD];
    const int tid = threadIdx.x;
    const int n0 = blockIdx.x * 16;

    for (int idx = tid; idx < 16 * FIN; idx += 128) {
        int e = idx / FIN, k = idx - e * FIN;
        s_in[idx] = nf[(n0 + e) * FIN + k];
    }
    __syncthreads();

    const int j = tid;
    float acc[16];
#pragma unroll
    for (int e = 0; e < 16; e++) acc[e] = 0.0f;
    for (int k = 0; k < FIN; k++) {
        float w = W1[k * DD + j];
#pragma unroll
        for (int e = 0; e < 16; e++) acc[e] = fmaf(s_in[e * FIN + k], w, acc[e]);
    }
    float bb1 = b1[j];
#pragma unroll
    for (int e = 0; e < 16; e++) s_hid[e * DD + j] = silu_f(acc[e] + bb1);
    __syncthreads();

    float acc2[16];
#pragma unroll
    for (int e = 0; e < 16; e++) acc2[e] = 0.0f;
    const float4* sh4 = (const float4*)s_hid;
    for (int k4 = 0; k4 < DD / 4; k4++) {
        const float* wp = &W2[(k4 * 4) * DD + j];
        float w0 = wp[0], w1 = wp[DD], w2 = wp[2 * DD], w3 = wp[3 * DD];
#pragma unroll
        for (int e = 0; e < 16; e++) {
            float4 a = sh4[e * (DD / 4) + k4];
            acc2[e] = fmaf(a.x, w0, acc2[e]);
            acc2[e] = fmaf(a.y, w1, acc2[e]);
            acc2[e] = fmaf(a.z, w2, acc2[e]);
            acc2[e] = fmaf(a.w, w3, acc2[e]);
        }
    }
    float bb2 = b2[j];
#pragma unroll
    for (int e = 0; e < 16; e++) h[(n0 + e) * DD + j] = acc2[e] + bb2;
}

// ---------------- per-edge RBF features (E,16), tf32-rounded ---------------
__global__ void rbf_k(const float* __restrict__ pos, const int* __restrict__ EI,
                      float* __restrict__ ef)
{
    int e = blockIdx.x * blockDim.x + threadIdx.x;
    if (e >= EE) return;
    int s = EI[e];
    int d = EI[EE + e];
    float dx = pos[d * 3 + 0] - pos[s * 3 + 0];
    float dy = pos[d * 3 + 1] - pos[s * 3 + 1];
    float dz = pos[d * 3 + 2] - pos[s * 3 + 2];
    float dist = sqrtf(dx * dx + dy * dy + dz * dz + 1e-12f);
    float env = (dist < 10.0f)
                    ? 0.5f * (cosf(3.14159265358979323846f * dist * 0.1f) + 1.0f)
                    : 0.0f;
    const float inv2w2 = 1.0f / (2.0f * 0.625f * 0.625f);
#pragma unroll
    for (int k = 0; k < NRBF; k++) {
        float c = (10.0f / 15.0f) * (float)k;
        float t = dist - c;
        ef[e * NRBF + k] = to_tf32(__expf(-t * t * inv2w2) * env);
    }
}

// ---------------- tensor-core (mma.sync) message MLP + scatter ---------------
// CTA: 128 edges, 512 threads = 16 warps.
// GEMM1: [128 x 288] @ [288 x 256] -> silu -> GEMM2: [128 x 256] @ [256 x 128]
// A-frag for m16n8k8 (element (r,c), r<16, c<8):
//   t = (r%8)*4 + (c%4); reg = (r/8) + 2*(c/4)
// A_perm[mt][kc][t][4] (uint4 per thread -> one lds.128 per frag)
__global__ void __launch_bounds__(512, 1) msg_mma_k(
    const int* __restrict__ EI,
    const float* __restrict__ h, const float* __restrict__ ef,
    const float* __restrict__ W1f, const float* __restrict__ b1,
    const float* __restrict__ W2f, const float* __restrict__ b2,
    float* __restrict__ agg)
{
    extern __shared__ __align__(16) float sA[];   // 8*36*32*4 floats = 147456 B
    __shared__ float s_b1[HH];
    __shared__ float s_b2[DD];
    __shared__ int   s_dst[128];

    const int tid = threadIdx.x;
    const int e0 = blockIdx.x * 128;

    if (tid < HH) s_b1[tid] = b1[tid];
    if (tid < DD) s_b2[tid] = b2[tid];
    if (tid < 128) s_dst[tid] = EI[EE + e0 + tid];

    // ---- stage A (gathered edge features) into A-fragment layout ----
    {
        const int e = tid >> 2;            // 0..127
        const int q = tid & 3;             // quarter of the 288-wide row
        const int src = EI[e0 + e];
        const int dst = EI[EE + e0 + e];
        const float* hs = h + (size_t)src * DD;
        const float* hd = h + (size_t)dst * DD;
        const float* ep = ef + (size_t)(e0 + e) * NRBF;
        const int r = e & 15, mt = e >> 4;
#pragma unroll
        for (int j = 0; j < 18; j++) {
            int k0 = j * 16 + q * 4;       // multiple of 4, covers 0..284
            float4 v;
            if (k0 < 128)       v = *(const float4*)(hs + k0);
            else if (k0 < 256)  v = *(const float4*)(hd + (k0 - 128));
            else if (k0 < 272)  v = *(const float4*)(ep + (k0 - 256));
            else                v = make_float4(0.f, 0.f, 0.f, 0.f);
            if (k0 < 256) {
                v.x = to_tf32(v.x); v.y = to_tf32(v.y);
                v.z = to_tf32(v.z); v.w = to_tf32(v.w);
            }
            int kc = k0 >> 3;
            int ii = (r >> 3) + ((k0 & 4) ? 2 : 0);
            float* p = sA + (((mt * KC1 + kc) * 32) + ((r & 7) * 4)) * 4 + ii;
            p[0] = v.x; p[4] = v.y; p[8] = v.z; p[12] = v.w;
        }
    }
    __syncthreads();

    const int wid = tid >> 5, lane = tid & 31;
    const int wm = wid >> 2, wn = wid & 3;   // 4 M-tiles(32) x 4 N-tiles

    // ================= GEMM1: N-tile = 64 (8 frags), M-tile = 32 ============
    float acc[2][8][4];
#pragma unroll
    for (int a = 0; a < 2; a++)
#pragma unroll
        for (int b = 0; b < 8; b++)
#pragma unroll
            for (int c = 0; c < 4; c++) acc[a][b][c] = 0.0f;
    {
        const uint4* a0p = (const uint4*)sA + (wm * 2 + 0) * KC1 * 32 + lane;
        const uint4* a1p = (const uint4*)sA + (wm * 2 + 1) * KC1 * 32 + lane;
        const uint4* bp = (const uint4*)W1f + (wn * 4) * 32 + lane;
#pragma unroll 2
        for (int kc = 0; kc < KC1; kc++) {
            uint4 bf0 = bp[kc * 512 + 0];
            uint4 bf1 = bp[kc * 512 + 32];
            uint4 bf2 = bp[kc * 512 + 64];
            uint4 bf3 = bp[kc * 512 + 96];
            uint4 a0 = a0p[kc * 32];
            uint4 a1 = a1p[kc * 32];
            mma8(acc[0][0], a0, bf0.x, bf0.y);  mma8(acc[0][1], a0, bf0.z, bf0.w);
            mma8(acc[0][2], a0, bf1.x, bf1.y);  mma8(acc[0][3], a0, bf1.z, bf1.w);
            mma8(acc[0][4], a0, bf2.x, bf2.y);  mma8(acc[0][5], a0, bf2.z, bf2.w);
            mma8(acc[0][6], a0, bf3.x, bf3.y);  mma8(acc[0][7], a0, bf3.z, bf3.w);
            mma8(acc[1][0], a1, bf0.x, bf0.y);  mma8(acc[1][1], a1, bf0.z, bf0.w);
            mma8(acc[1][2], a1, bf1.x, bf1.y);  mma8(acc[1][3], a1, bf1.z, bf1.w);
            mma8(acc[1][4], a1, bf2.x, bf2.y);  mma8(acc[1][5], a1, bf2.z, bf2.w);
            mma8(acc[1][6], a1, bf3.x, bf3.y);  mma8(acc[1][7], a1, bf3.z, bf3.w);
        }
    }
    __syncthreads();   // all warps done reading A1 from sA

    // ---- epilogue1: bias + silu -> A2-fragment layout in sA ----
#pragma unroll
    for (int mi = 0; mi < 2; mi++)
#pragma unroll
        for (int nf = 0; nf < 8; nf++)
#pragma unroll
            for (int j = 0; j < 4; j++) {
                int m = wm * 32 + mi * 16 + (lane >> 2) + ((j >> 1) << 3);
                int n = wn * 64 + nf * 8 + ((lane & 3) << 1) + (j & 1);
                float y = to_tf32(silu_f(acc[mi][nf][j] + s_b1[n]));
                int r2 = m & 15, mt2 = m >> 4, kc2 = n >> 3, c2 = n & 7;
                int t2 = ((r2 & 7) << 2) + (c2 & 3);
                int i2 = (r2 >> 3) + ((c2 >> 2) << 1);
                sA[((mt2 * KC2 + kc2) * 32 + t2) * 4 + i2] = y;
            }
    __syncthreads();

    // ================= GEMM2: N-tile = 32 (4 frags), M-tile = 32 ============
    float acc2[2][4][4];
#pragma unroll
    for (int a = 0; a < 2; a++)
#pragma unroll
        for (int b = 0; b < 4; b++)
#pragma unroll
            for (int c = 0; c < 4; c++) acc2[a][b][c] = 0.0f;
    {
        const uint4* a0p = (const uint4*)sA + (wm * 2 + 0) * KC2 * 32 + lane;
        const uint4* a1p = (const uint4*)sA + (wm * 2 + 1) * KC2 * 32 + lane;
        const uint4* bp = (const uint4*)W2f + (wn * 2) * 32 + lane;
#pragma unroll 2
        for (int kc = 0; kc < KC2; kc++) {
            uint4 bf0 = bp[kc * 256 + 0];
            uint4 bf1 = bp[kc * 256 + 32];
            uint4 a0 = a0p[kc * 32];
            uint4 a1 = a1p[kc * 32];
            mma8(acc2[0][0], a0, bf0.x, bf0.y);  mma8(acc2[0][1], a0, bf0.z, bf0.w);
            mma8(acc2[0][2], a0, bf1.x, bf1.y);  mma8(acc2[0][3], a0, bf1.z, bf1.w);
            mma8(acc2[1][0], a1, bf0.x, bf0.y);  mma8(acc2[1][1], a1, bf0.z, bf0.w);
            mma8(acc2[1][2], a1, bf1.x, bf1.y);  mma8(acc2[1][3], a1, bf1.z, bf1.w);
        }
    }

    // ---- epilogue2: bias + atomic scatter to agg[dst] ----
#pragma unroll
    for (int mi = 0; mi < 2; mi++)
#pragma unroll
        for (int nf = 0; nf < 4; nf++)
#pragma unroll
            for (int j = 0; j < 4; j++) {
                int m = wm * 32 + mi * 16 + (lane >> 2) + ((j >> 1) << 3);
                int n = wn * 32 + nf * 8 + ((lane & 3) << 1) + (j & 1);
                atomicAdd(agg + (size_t)s_dst[m] * DD + n, acc2[mi][nf][j] + s_b2[n]);
            }
}

// ---------------- node update MLP (residual, in-place, fp32) ----------------
__global__ void __launch_bounds__(256) upd_k(
    float* __restrict__ h, const float* __restrict__ agg,
    const float* __restrict__ W1, const float* __restrict__ b1,
    const float* __restrict__ W2, const float* __restrict__ b2)
{
    __shared__ __align__(16) float s_in[16 * 2 * DD];
    __shared__ __align__(16) float s_hid[16 * HH];
    const int tid = threadIdx.x;
    const int n0 = blockIdx.x * 16;

    for (int idx = tid; idx < 16 * 2 * DD; idx += 256) {
        int e = idx >> 8, k = idx & 255;
        float v = (k < DD) ? h[(n0 + e) * DD + k] : agg[(n0 + e) * DD + (k - DD)];
        s_in[idx] = v;
    }
    __syncthreads();

    {
        const int j = tid;
        float acc[16];
#pragma unroll
        for (int e = 0; e < 16; e++) acc[e] = 0.0f;
        const float4* si4 = (const float4*)s_in;
        for (int k4 = 0; k4 < (2 * DD) / 4; k4++) {
            const float* wp = &W1[(k4 * 4) * HH + j];
            float w0 = wp[0], w1 = wp[HH], w2 = wp[2 * HH], w3 = wp[3 * HH];
#pragma unroll
            for (int e = 0; e < 16; e++) {
                float4 a = si4[e * ((2 * DD) / 4) + k4];
                acc[e] = fmaf(a.x, w0, acc[e]);
                acc[e] = fmaf(a.y, w1, acc[e]);
                acc[e] = fmaf(a.z, w2, acc[e]);
                acc[e] = fmaf(a.w, w3, acc[e]);
            }
        }
        float bb = b1[j];
#pragma unroll
        for (int e = 0; e < 16; e++) s_hid[e * HH + j] = silu_f(acc[e] + bb);
    }
    __syncthreads();

    {
        const int j = tid & (DD - 1);
        const int eb = (tid >> 7) * 8;
        float acc[8];
#pragma unroll
        for (int e = 0; e < 8; e++) acc[e] = 0.0f;
        const float4* sh4 = (const float4*)s_hid;
        for (int k4 = 0; k4 < HH / 4; k4++) {
            const float* wp = &W2[(k4 * 4) * DD + j];
            float w0 = wp[0], w1 = wp[DD], w2 = wp[2 * DD], w3 = wp[3 * DD];
#pragma unroll
            for (int e = 0; e < 8; e++) {
                float4 a = sh4[(eb + e) * (HH / 4) + k4];
                acc[e] = fmaf(a.x, w0, acc[e]);
                acc[e] = fmaf(a.y, w1, acc[e]);
                acc[e] = fmaf(a.z, w2, acc[e]);
                acc[e] = fmaf(a.w, w3, acc[e]);
            }
        }
        float bb = b2[j];
#pragma unroll
        for (int e = 0; e < 8; e++)
            h[(n0 + eb + e) * DD + j] += acc[e] + bb;
    }
}

// ---------------- per-graph counts ------------------------------------------
__global__ void cnt_k(const int* __restrict__ batch, float* __restrict__ cnt)
{
    int n = blockIdx.x * blockDim.x + threadIdx.x;
    if (n < NN) atomicAdd(&cnt[batch[n]], 1.0f);
}

// ---------------- per-graph feature sums ------------------------------------
__global__ void __launch_bounds__(128) gsum_k(
    const float* __restrict__ h, const int* __restrict__ batch,
    float* __restrict__ gsum)
{
    const int j = threadIdx.x;
    const int n0 = blockIdx.x * 32;
    int curb = batch[n0];
    float acc = 0.0f;
    for (int i = 0; i < 32; i++) {
        int n = n0 + i;
        int b = batch[n];
        if (b != curb) {
            atomicAdd(&gsum[curb * DD + j], acc);
            acc = 0.0f;
            curb = b;
        }
        acc += h[n * DD + j];
    }
    atomicAdd(&gsum[curb * DD + j], acc);
}

// ---------------- readout MLP (single block) --------------------------------
__global__ void __launch_bounds__(256) final_k(
    const float* __restrict__ gsum, const float* __restrict__ cnt,
    const float* __restrict__ W1, const float* __restrict__ b1,
    const float* __restrict__ W2, const float* __restrict__ b2,
    float* __restrict__ out)
{
    __shared__ float sg[BB * DD];
    __shared__ float sh[BB * HH];
    const int tid = threadIdx.x;

    for (int idx = tid; idx < BB * DD; idx += 256) {
        int b = idx >> 7;
        sg[idx] = gsum[idx] / fmaxf(cnt[b], 1.0f);
    }
    __syncthreads();

    {
        const int j = tid;
        float acc[BB];
#pragma unroll
        for (int b = 0; b < BB; b++) acc[b] = 0.0f;
        for (int k = 0; k < DD; k++) {
            float w = W1[k * HH + j];
#pragma unroll
            for (int b = 0; b < BB; b++) acc[b] = fmaf(sg[b * DD + k], w, acc[b]);
        }
        float bb = b1[j];
#pragma unroll
        for (int b = 0; b < BB; b++) sh[b * HH + j] = silu_f(acc[b] + bb);
    }
    __syncthreads();

    if (tid < OUTD) {
        const int j = tid;
        float acc[BB];
#pragma unroll
        for (int b = 0; b < BB; b++) acc[b] = 0.0f;
        for (int k = 0; k < HH; k++) {
            float w = W2[k * OUTD + j];
#pragma unroll
            for (int b = 0; b < BB; b++) acc[b] = fmaf(sh[b * HH + k], w, acc[b]);
        }
        float bb = b2[j];
#pragma unroll
        for (int b = 0; b < BB; b++) out[b * OUTD + j] = acc[b] + bb;
    }
}

// ---------------- launch -----------------------------------------------------
#define SMEM_MSG (8 * KC1 * 32 * 4 * 4)   // 147456 bytes

extern "C" void kernel_launch(void* const* d_in, const int* in_sizes, int n_in,
                              void* d_out, int out_size)
{
    const float* pos    = (const float*)d_in[0];
    const float* nf     = (const float*)d_in[1];
    const int*   EI     = (const int*)d_in[2];
    const int*   batch  = (const int*)d_in[3];
    const float* emb_W1 = (const float*)d_in[4];
    const float* emb_b1 = (const float*)d_in[5];
    const float* emb_W2 = (const float*)d_in[6];
    const float* emb_b2 = (const float*)d_in[7];
    const float* msg_W1 = (const float*)d_in[8];
    const float* msg_b1 = (const float*)d_in[9];
    const float* msg_W2 = (const float*)d_in[10];
    const float* msg_b2 = (const float*)d_in[11];
    const float* upd_W1 = (const float*)d_in[12];
    const float* upd_b1 = (const float*)d_in[13];
    const float* upd_W2 = (const float*)d_in[14];
    const float* upd_b2 = (const float*)d_in[15];
    const float* r_W1   = (const float*)d_in[16];
    const float* r_b1   = (const float*)d_in[17];
    const float* r_W2   = (const float*)d_in[18];
    const float* r_b2   = (const float*)d_in[19];
    float* out = (float*)d_out;

    void *p_h, *p_agg, *p_ef, *p_gsum, *p_gcnt, *p_w1f, *p_w2f;
    cudaGetSymbolAddress(&p_h, g_h);
    cudaGetSymbolAddress(&p_agg, g_agg);
    cudaGetSymbolAddress(&p_ef, g_ef);
    cudaGetSymbolAddress(&p_gsum, g_gsum);
    cudaGetSymbolAddress(&p_gcnt, g_gcnt);
    cudaGetSymbolAddress(&p_w1f, g_W1f);
    cudaGetSymbolAddress(&p_w2f, g_W2f);
    float* h    = (float*)p_h;
    float* agg  = (float*)p_agg;
    float* ef   = (float*)p_ef;
    float* gsum = (float*)p_gsum;
    float* gcnt = (float*)p_gcnt;
    float* W1f  = (float*)p_w1f;
    float* W2f  = (float*)p_w2f;

    cudaFuncSetAttribute(msg_mma_k, cudaFuncAttributeMaxDynamicSharedMemorySize, SMEM_MSG);

    prep1_k<<<(NL * KC1 * 16 * 32 * 4 + 255) / 256, 256>>>(msg_W1, W1f);
    prep2_k<<<(NL * KC2 * 8 * 32 * 4 + 255) / 256, 256>>>(msg_W2, W2f);
    embed_k<<<NN / 16, 128>>>(nf, emb_W1, emb_b1, emb_W2, emb_b2, h);
    rbf_k<<<EE / 256, 256>>>(pos, EI, ef);

    for (int l = 0; l < NL; l++) {
        cudaMemsetAsync(agg, 0, (size_t)NN * DD * sizeof(float), 0);
        msg_mma_k<<<EE / 128, 512, SMEM_MSG>>>(
            EI, h, ef,
            W1f + (size_t)l * KC1 * 16 * 32 * 4,
            msg_b1 + (size_t)l * HH,
            W2f + (size_t)l * KC2 * 8 * 32 * 4,
            msg_b2 + (size_t)l * DD,
            agg);
        upd_k<<<NN / 16, 256>>>(h, agg,
                                upd_W1 + (size_t)l * 2 * DD * HH,
                                upd_b1 + (size_t)l * HH,
                                upd_W2 + (size_t)l * HH * DD,
                                upd_b2 + (size_t)l * DD);
    }

    cudaMemsetAsync(gsum, 0, (size_t)BB * DD * sizeof(float), 0);
    cudaMemsetAsync(gcnt, 0, (size_t)BB * sizeof(float), 0);
    cnt_k<<<NN / 256, 256>>>(batch, gcnt);
    gsum_k<<<NN / 32, 128>>>(h, batch, gsum);
    final_k<<<1, 256>>>(gsum, gcnt, r_W1, r_b1, r_W2, r_b2, out);
}

// round 5
// speedup vs baseline: 3.6704x; 1.0685x over previous
#include <cuda_runtime.h>
#include <math.h>
#include <stdint.h>

#define NN    16384
#define EE    524288
#define BB    8
#define FIN   26
#define DD    128
#define HH    256
#define OUTD  64
#define NL    4
#define NRBF  16
#define KIN   272          // 2*DD + NRBF
#define KC1   36           // msg GEMM1 k-chunks of 8 (K padded to 288)
#define KC2   32           // GEMM2 / upd k-chunks of 8 (K = 256)

// ---------------- scratch (device globals; no allocation allowed) ----------
__device__ float g_h[NN * DD];
__device__ float g_agg[NN * DD];
__device__ float g_ef[EE * NRBF];
__device__ float g_gsum[BB * DD];
__device__ float g_gcnt[BB];
// msg weights in B-fragment layout (tf32)
__device__ float g_W1f[NL * KC1 * 16 * 32 * 4];   // [l][kc][npair16][t32][i4]
__device__ float g_W2f[NL * KC2 * 8 * 32 * 4];    // [l][kc][npair8][t32][i4]
// upd weights in B-fragment layout (tf32)
__device__ float g_WU1f[NL * 32 * 16 * 32 * 4];   // K=256,N=256
__device__ float g_WU2f[NL * 32 * 8 * 32 * 4];    // K=256,N=128

__device__ __forceinline__ float silu_f(float x) {
    return x * (1.0f / (1.0f + __expf(-x)));
}
__device__ __forceinline__ float to_tf32(float x) {
    uint32_t u;
    asm volatile("cvt.rna.tf32.f32 %0, %1;" : "=r"(u) : "f"(x));
    return __uint_as_float(u);
}

// m16n8k8 tf32 MMA (baseline PTX, valid on compute_103)
__device__ __forceinline__ void mma8(float* c, uint4 a, uint32_t b0, uint32_t b1) {
    asm volatile(
        "mma.sync.aligned.m16n8k8.row.col.f32.tf32.tf32.f32 "
        "{%0,%1,%2,%3}, {%4,%5,%6,%7}, {%8,%9}, {%0,%1,%2,%3};"
        : "+f"(c[0]), "+f"(c[1]), "+f"(c[2]), "+f"(c[3])
        : "r"(a.x), "r"(a.y), "r"(a.z), "r"(a.w), "r"(b0), "r"(b1));
}

__device__ __forceinline__ void red4(float* p, float4 v) {
    asm volatile("red.global.add.v4.f32 [%0], {%1,%2,%3,%4};"
                 :: "l"(p), "f"(v.x), "f"(v.y), "f"(v.z), "f"(v.w) : "memory");
}

// ---------------- weight prep: fragment layout, tf32 ------------------------
// B-frag m16n8k8: b0 -> (k=t%4, n=t/4), b1 -> (k=t%4+4, n=t/4)
// packed npairs: [kc][np][t][i]: i=0,1 -> frag 2p; i=2,3 -> frag 2p+1
__global__ void prep1_k(const float* __restrict__ W1, float* __restrict__ W1f) {
    int idx = blockIdx.x * 256 + threadIdx.x;
    const int PER = KC1 * 16 * 32 * 4;
    if (idx >= NL * PER) return;
    int l = idx / PER, r = idx - l * PER;
    int kc = r / 2048;  r -= kc * 2048;
    int np = r / 128;   r -= np * 128;
    int t = r / 4, i = r & 3;
    int k = kc * 8 + (t & 3) + 4 * (i & 1);
    int n = (np * 2 + (i >> 1)) * 8 + (t >> 2);
    W1f[idx] = (k < KIN) ? to_tf32(W1[((size_t)l * KIN + k) * HH + n]) : 0.0f;
}
__global__ void prep2_k(const float* __restrict__ W2, float* __restrict__ W2f) {
    int idx = blockIdx.x * 256 + threadIdx.x;
    const int PER = KC2 * 8 * 32 * 4;
    if (idx >= NL * PER) return;
    int l = idx / PER, r = idx - l * PER;
    int kc = r / 1024;  r -= kc * 1024;
    int np = r / 128;   r -= np * 128;
    int t = r / 4, i = r & 3;
    int k = kc * 8 + (t & 3) + 4 * (i & 1);
    int n = (np * 2 + (i >> 1)) * 8 + (t >> 2);
    W2f[idx] = to_tf32(W2[((size_t)l * HH + k) * DD + n]);
}
__global__ void prepU1_k(const float* __restrict__ W1, float* __restrict__ W1f) {
    int idx = blockIdx.x * 256 + threadIdx.x;
    const int PER = 32 * 16 * 32 * 4;
    if (idx >= NL * PER) return;
    int l = idx / PER, r = idx - l * PER;
    int kc = r / 2048;  r -= kc * 2048;
    int np = r / 128;   r -= np * 128;
    int t = r / 4, i = r & 3;
    int k = kc * 8 + (t & 3) + 4 * (i & 1);
    int n = (np * 2 + (i >> 1)) * 8 + (t >> 2);
    W1f[idx] = to_tf32(W1[((size_t)l * 256 + k) * HH + n]);
}
__global__ void prepU2_k(const float* __restrict__ W2, float* __restrict__ W2f) {
    int idx = blockIdx.x * 256 + threadIdx.x;
    const int PER = 32 * 8 * 32 * 4;
    if (idx >= NL * PER) return;
    int l = idx / PER, r = idx - l * PER;
    int kc = r / 1024;  r -= kc * 1024;
    int np = r / 128;   r -= np * 128;
    int t = r / 4, i = r & 3;
    int k = kc * 8 + (t & 3) + 4 * (i & 1);
    int n = (np * 2 + (i >> 1)) * 8 + (t >> 2);
    W2f[idx] = to_tf32(W2[((size_t)l * HH + k) * DD + n]);
}

// ---------------- node embedding: (N,26) -> silu -> (N,128) ----------------
__global__ void __launch_bounds__(128) embed_k(
    const float* __restrict__ nf,
    const float* __restrict__ W1, const float* __restrict__ b1,
    const float* __restrict__ W2, const float* __restrict__ b2,
    float* __restrict__ h)
{
    __shared__ __align__(16) float s_in[16 * FIN];
    __shared__ __align__(16) float s_hid[16 * DD];
    const int tid = threadIdx.x;
    const int n0 = blockIdx.x * 16;

    for (int idx = tid; idx < 16 * FIN; idx += 128) {
        int e = idx / FIN, k = idx - e * FIN;
        s_in[idx] = nf[(n0 + e) * FIN + k];
    }
    __syncthreads();

    const int j = tid;
    float acc[16];
#pragma unroll
    for (int e = 0; e < 16; e++) acc[e] = 0.0f;
    for (int k = 0; k < FIN; k++) {
        float w = W1[k * DD + j];
#pragma unroll
        for (int e = 0; e < 16; e++) acc[e] = fmaf(s_in[e * FIN + k], w, acc[e]);
    }
    float bb1 = b1[j];
#pragma unroll
    for (int e = 0; e < 16; e++) s_hid[e * DD + j] = silu_f(acc[e] + bb1);
    __syncthreads();

    float acc2[16];
#pragma unroll
    for (int e = 0; e < 16; e++) acc2[e] = 0.0f;
    const float4* sh4 = (const float4*)s_hid;
    for (int k4 = 0; k4 < DD / 4; k4++) {
        const float* wp = &W2[(k4 * 4) * DD + j];
        float w0 = wp[0], w1 = wp[DD], w2 = wp[2 * DD], w3 = wp[3 * DD];
#pragma unroll
        for (int e = 0; e < 16; e++) {
            float4 a = sh4[e * (DD / 4) + k4];
            acc2[e] = fmaf(a.x, w0, acc2[e]);
            acc2[e] = fmaf(a.y, w1, acc2[e]);
            acc2[e] = fmaf(a.z, w2, acc2[e]);
            acc2[e] = fmaf(a.w, w3, acc2[e]);
        }
    }
    float bb2 = b2[j];
#pragma unroll
    for (int e = 0; e < 16; e++) h[(n0 + e) * DD + j] = acc2[e] + bb2;
}

// ---------------- per-edge RBF features (E,16), tf32-rounded ---------------
__global__ void rbf_k(const float* __restrict__ pos, const int* __restrict__ EI,
                      float* __restrict__ ef)
{
    int e = blockIdx.x * blockDim.x + threadIdx.x;
    if (e >= EE) return;
    int s = EI[e];
    int d = EI[EE + e];
    float dx = pos[d * 3 + 0] - pos[s * 3 + 0];
    float dy = pos[d * 3 + 1] - pos[s * 3 + 1];
    float dz = pos[d * 3 + 2] - pos[s * 3 + 2];
    float dist = sqrtf(dx * dx + dy * dy + dz * dz + 1e-12f);
    float env = (dist < 10.0f)
                    ? 0.5f * (cosf(3.14159265358979323846f * dist * 0.1f) + 1.0f)
                    : 0.0f;
    const float inv2w2 = 1.0f / (2.0f * 0.625f * 0.625f);
#pragma unroll
    for (int k = 0; k < NRBF; k++) {
        float c = (10.0f / 15.0f) * (float)k;
        float t = dist - c;
        ef[e * NRBF + k] = to_tf32(__expf(-t * t * inv2w2) * env);
    }
}

// ---------------- tensor-core message MLP + v4-red scatter -------------------
// CTA: 128 edges, 512 threads = 16 warps (2M x 8N).
__global__ void __launch_bounds__(512, 1) msg_mma_k(
    const int* __restrict__ EI,
    const float* __restrict__ h, const float* __restrict__ ef,
    const float* __restrict__ W1f, const float* __restrict__ b1,
    const float* __restrict__ W2f, const float* __restrict__ b2,
    float* __restrict__ agg)
{
    extern __shared__ __align__(16) float sA[];   // 147456 B (KC1 layout)
    __shared__ float s_b1[HH];
    __shared__ float s_b2[DD];
    __shared__ int   s_dst[128];

    const int tid = threadIdx.x;
    const int e0 = blockIdx.x * 128;

    if (tid < HH) s_b1[tid] = b1[tid];
    if (tid < DD) s_b2[tid] = b2[tid];
    if (tid < 128) s_dst[tid] = EI[EE + e0 + tid];

    // ---- stage gathered A into fragment layout ----
    {
        const int e = tid >> 2;
        const int q = tid & 3;
        const int src = EI[e0 + e];
        const int dst = EI[EE + e0 + e];
        const float* hs = h + (size_t)src * DD;
        const float* hd = h + (size_t)dst * DD;
        const float* ep = ef + (size_t)(e0 + e) * NRBF;
        const int r = e & 15, mt = e >> 4;
#pragma unroll
        for (int j = 0; j < 18; j++) {
            int k0 = j * 16 + q * 4;
            float4 v;
            if (k0 < 128)       v = *(const float4*)(hs + k0);
            else if (k0 < 256)  v = *(const float4*)(hd + (k0 - 128));
            else if (k0 < 272)  v = *(const float4*)(ep + (k0 - 256));
            else                v = make_float4(0.f, 0.f, 0.f, 0.f);
            if (k0 < 256) {
                v.x = to_tf32(v.x); v.y = to_tf32(v.y);
                v.z = to_tf32(v.z); v.w = to_tf32(v.w);
            }
            int kc = k0 >> 3;
            int ii = (r >> 3) + ((k0 & 4) ? 2 : 0);
            float* p = sA + (((mt * KC1 + kc) * 32) + ((r & 7) * 4)) * 4 + ii;
            p[0] = v.x; p[4] = v.y; p[8] = v.z; p[12] = v.w;
        }
    }
    __syncthreads();

    const int wid = tid >> 5, lane = tid & 31;
    const int wm = wid >> 3, wn = wid & 7;   // 2 M-tiles(64) x 8 N-tiles

    // ================= GEMM1: M-tile 64 (4 mfrags), N-tile 32 (2 npairs) ====
    float acc[4][4][4];
#pragma unroll
    for (int a = 0; a < 4; a++)
#pragma unroll
        for (int b = 0; b < 4; b++)
#pragma unroll
            for (int c = 0; c < 4; c++) acc[a][b][c] = 0.0f;
    {
        const uint4* ap0 = (const uint4*)sA + (wm * 4 + 0) * KC1 * 32 + lane;
        const uint4* ap1 = (const uint4*)sA + (wm * 4 + 1) * KC1 * 32 + lane;
        const uint4* ap2 = (const uint4*)sA + (wm * 4 + 2) * KC1 * 32 + lane;
        const uint4* ap3 = (const uint4*)sA + (wm * 4 + 3) * KC1 * 32 + lane;
        const uint4* bp = (const uint4*)W1f + (wn * 2) * 32 + lane;
#pragma unroll 2
        for (int kc = 0; kc < KC1; kc++) {
            uint4 b0 = bp[kc * 512];
            uint4 b1v = bp[kc * 512 + 32];
            uint4 a0 = ap0[kc * 32], a1 = ap1[kc * 32];
            uint4 a2 = ap2[kc * 32], a3 = ap3[kc * 32];
            mma8(acc[0][0], a0, b0.x, b0.y);  mma8(acc[0][1], a0, b0.z, b0.w);
            mma8(acc[0][2], a0, b1v.x, b1v.y); mma8(acc[0][3], a0, b1v.z, b1v.w);
            mma8(acc[1][0], a1, b0.x, b0.y);  mma8(acc[1][1], a1, b0.z, b0.w);
            mma8(acc[1][2], a1, b1v.x, b1v.y); mma8(acc[1][3], a1, b1v.z, b1v.w);
            mma8(acc[2][0], a2, b0.x, b0.y);  mma8(acc[2][1], a2, b0.z, b0.w);
            mma8(acc[2][2], a2, b1v.x, b1v.y); mma8(acc[2][3], a2, b1v.z, b1v.w);
            mma8(acc[3][0], a3, b0.x, b0.y);  mma8(acc[3][1], a3, b0.z, b0.w);
            mma8(acc[3][2], a3, b1v.x, b1v.y); mma8(acc[3][3], a3, b1v.z, b1v.w);
        }
    }
    __syncthreads();

    // ---- epilogue1: bias + silu -> A2-fragment layout (KC2) ----
#pragma unroll
    for (int mi = 0; mi < 4; mi++)
#pragma unroll
        for (int nf = 0; nf < 4; nf++)
#pragma unroll
            for (int j = 0; j < 4; j++) {
                int m = wm * 64 + mi * 16 + (lane >> 2) + ((j >> 1) << 3);
                int n = wn * 32 + nf * 8 + ((lane & 3) << 1) + (j & 1);
                float y = to_tf32(silu_f(acc[mi][nf][j] + s_b1[n]));
                int r2 = m & 15, mt2 = m >> 4, kc2 = n >> 3, c2 = n & 7;
                int t2 = ((r2 & 7) << 2) + (c2 & 3);
                int i2 = (r2 >> 3) + ((c2 >> 2) << 1);
                sA[((mt2 * KC2 + kc2) * 32 + t2) * 4 + i2] = y;
            }
    __syncthreads();

    // ================= GEMM2: M-tile 64, N-tile 16 (1 npair) ================
    float acc2[4][2][4];
#pragma unroll
    for (int a = 0; a < 4; a++)
#pragma unroll
        for (int b = 0; b < 2; b++)
#pragma unroll
            for (int c = 0; c < 4; c++) acc2[a][b][c] = 0.0f;
    {
        const uint4* ap0 = (const uint4*)sA + (wm * 4 + 0) * KC2 * 32 + lane;
        const uint4* ap1 = (const uint4*)sA + (wm * 4 + 1) * KC2 * 32 + lane;
        const uint4* ap2 = (const uint4*)sA + (wm * 4 + 2) * KC2 * 32 + lane;
        const uint4* ap3 = (const uint4*)sA + (wm * 4 + 3) * KC2 * 32 + lane;
        const uint4* bp = (const uint4*)W2f + wn * 32 + lane;
#pragma unroll 2
        for (int kc = 0; kc < KC2; kc++) {
            uint4 b = bp[kc * 256];
            uint4 a0 = ap0[kc * 32], a1 = ap1[kc * 32];
            uint4 a2 = ap2[kc * 32], a3 = ap3[kc * 32];
            mma8(acc2[0][0], a0, b.x, b.y);  mma8(acc2[0][1], a0, b.z, b.w);
            mma8(acc2[1][0], a1, b.x, b.y);  mma8(acc2[1][1], a1, b.z, b.w);
            mma8(acc2[2][0], a2, b.x, b.y);  mma8(acc2[2][1], a2, b.z, b.w);
            mma8(acc2[3][0], a3, b.x, b.y);  mma8(acc2[3][1], a3, b.z, b.w);
        }
    }
    __syncthreads();   // sA free -> reuse as D2 staging [128][128]

    // ---- epilogue2: stage D2+bias, then red.v4 scatter ----
#pragma unroll
    for (int mi = 0; mi < 4; mi++)
#pragma unroll
        for (int nf = 0; nf < 2; nf++)
#pragma unroll
            for (int j = 0; j < 4; j++) {
                int m = wm * 64 + mi * 16 + (lane >> 2) + ((j >> 1) << 3);
                int n = wn * 16 + nf * 8 + ((lane & 3) << 1) + (j & 1);
                sA[m * DD + n] = acc2[mi][nf][j] + s_b2[n];
            }
    __syncthreads();
    {
        const int cc = tid & 31;
        const int r0 = tid >> 5;
#pragma unroll
        for (int it = 0; it < 8; it++) {
            int r = r0 + it * 16;
            float4 v = *(const float4*)(sA + r * DD + cc * 4);
            red4(agg + (size_t)s_dst[r] * DD + cc * 4, v);
        }
    }
}

// ---------------- tensor-core update MLP (residual, no atomics) --------------
// CTA: 128 nodes, 512 threads = 16 warps (2M x 8N). K=256 both GEMMs.
__global__ void __launch_bounds__(512, 1) upd_mma_k(
    float* __restrict__ h, const float* __restrict__ agg,
    const float* __restrict__ W1f, const float* __restrict__ b1,
    const float* __restrict__ W2f, const float* __restrict__ b2)
{
    extern __shared__ __align__(16) float sA[];   // 131072 B
    __shared__ float s_b1[HH];
    __shared__ float s_b2[DD];

    const int tid = threadIdx.x;
    const int n0 = blockIdx.x * 128;

    if (tid < HH) s_b1[tid] = b1[tid];
    if (tid < DD) s_b2[tid] = b2[tid];

    // ---- stage [h | agg] rows into fragment layout (KC=32) ----
    {
        const int e = tid >> 2;
        const int q = tid & 3;
        const float* hs = h + (size_t)(n0 + e) * DD;
        const float* ag = agg + (size_t)(n0 + e) * DD;
        const int r = e & 15, mt = e >> 4;
#pragma unroll
        for (int j = 0; j < 16; j++) {
            int k0 = j * 16 + q * 4;
            float4 v = (k0 < 128) ? *(const float4*)(hs + k0)
                                  : *(const float4*)(ag + (k0 - 128));
            v.x = to_tf32(v.x); v.y = to_tf32(v.y);
            v.z = to_tf32(v.z); v.w = to_tf32(v.w);
            int kc = k0 >> 3;
            int ii = (r >> 3) + ((k0 & 4) ? 2 : 0);
            float* p = sA + (((mt * 32 + kc) * 32) + ((r & 7) * 4)) * 4 + ii;
            p[0] = v.x; p[4] = v.y; p[8] = v.z; p[12] = v.w;
        }
    }
    __syncthreads();

    const int wid = tid >> 5, lane = tid & 31;
    const int wm = wid >> 3, wn = wid & 7;

    // GEMM1 (K=256, N=256)
    float acc[4][4][4];
#pragma unroll
    for (int a = 0; a < 4; a++)
#pragma unroll
        for (int b = 0; b < 4; b++)
#pragma unroll
            for (int c = 0; c < 4; c++) acc[a][b][c] = 0.0f;
    {
        const uint4* ap0 = (const uint4*)sA + (wm * 4 + 0) * 32 * 32 + lane;
        const uint4* ap1 = (const uint4*)sA + (wm * 4 + 1) * 32 * 32 + lane;
        const uint4* ap2 = (const uint4*)sA + (wm * 4 + 2) * 32 * 32 + lane;
        const uint4* ap3 = (const uint4*)sA + (wm * 4 + 3) * 32 * 32 + lane;
        const uint4* bp = (const uint4*)W1f + (wn * 2) * 32 + lane;
#pragma unroll 2
        for (int kc = 0; kc < 32; kc++) {
            uint4 b0 = bp[kc * 512];
            uint4 b1v = bp[kc * 512 + 32];
            uint4 a0 = ap0[kc * 32], a1 = ap1[kc * 32];
            uint4 a2 = ap2[kc * 32], a3 = ap3[kc * 32];
            mma8(acc[0][0], a0, b0.x, b0.y);  mma8(acc[0][1], a0, b0.z, b0.w);
            mma8(acc[0][2], a0, b1v.x, b1v.y); mma8(acc[0][3], a0, b1v.z, b1v.w);
            mma8(acc[1][0], a1, b0.x, b0.y);  mma8(acc[1][1], a1, b0.z, b0.w);
            mma8(acc[1][2], a1, b1v.x, b1v.y); mma8(acc[1][3], a1, b1v.z, b1v.w);
            mma8(acc[2][0], a2, b0.x, b0.y);  mma8(acc[2][1], a2, b0.z, b0.w);
            mma8(acc[2][2], a2, b1v.x, b1v.y); mma8(acc[2][3], a2, b1v.z, b1v.w);
            mma8(acc[3][0], a3, b0.x, b0.y);  mma8(acc[3][1], a3, b0.z, b0.w);
            mma8(acc[3][2], a3, b1v.x, b1v.y); mma8(acc[3][3], a3, b1v.z, b1v.w);
        }
    }
    __syncthreads();

#pragma unroll
    for (int mi = 0; mi < 4; mi++)
#pragma unroll
        for (int nf = 0; nf < 4; nf++)
#pragma unroll
            for (int j = 0; j < 4; j++) {
                int m = wm * 64 + mi * 16 + (lane >> 2) + ((j >> 1) << 3);
                int n = wn * 32 + nf * 8 + ((lane & 3) << 1) + (j & 1);
                float y = to_tf32(silu_f(acc[mi][nf][j] + s_b1[n]));
                int r2 = m & 15, mt2 = m >> 4, kc2 = n >> 3, c2 = n & 7;
                int t2 = ((r2 & 7) << 2) + (c2 & 3);
                int i2 = (r2 >> 3) + ((c2 >> 2) << 1);
                sA[((mt2 * 32 + kc2) * 32 + t2) * 4 + i2] = y;
            }
    __syncthreads();

    // GEMM2 (K=256, N=128)
    float acc2[4][2][4];
#pragma unroll
    for (int a = 0; a < 4; a++)
#pragma unroll
        for (int b = 0; b < 2; b++)
#pragma unroll
            for (int c = 0; c < 4; c++) acc2[a][b][c] = 0.0f;
    {
        const uint4* ap0 = (const uint4*)sA + (wm * 4 + 0) * 32 * 32 + lane;
        const uint4* ap1 = (const uint4*)sA + (wm * 4 + 1) * 32 * 32 + lane;
        const uint4* ap2 = (const uint4*)sA + (wm * 4 + 2) * 32 * 32 + lane;
        const uint4* ap3 = (const uint4*)sA + (wm * 4 + 3) * 32 * 32 + lane;
        const uint4* bp = (const uint4*)W2f + wn * 32 + lane;
#pragma unroll 2
        for (int kc = 0; kc < 32; kc++) {
            uint4 b = bp[kc * 256];
            uint4 a0 = ap0[kc * 32], a1 = ap1[kc * 32];
            uint4 a2 = ap2[kc * 32], a3 = ap3[kc * 32];
            mma8(acc2[0][0], a0, b.x, b.y);  mma8(acc2[0][1], a0, b.z, b.w);
            mma8(acc2[1][0], a1, b.x, b.y);  mma8(acc2[1][1], a1, b.z, b.w);
            mma8(acc2[2][0], a2, b.x, b.y);  mma8(acc2[2][1], a2, b.z, b.w);
            mma8(acc2[3][0], a3, b.x, b.y);  mma8(acc2[3][1], a3, b.z, b.w);
        }
    }
    __syncthreads();

    // stage D2+bias, then coalesced residual add
#pragma unroll
    for (int mi = 0; mi < 4; mi++)
#pragma unroll
        for (int nf = 0; nf < 2; nf++)
#pragma unroll
            for (int j = 0; j < 4; j++) {
                int m = wm * 64 + mi * 16 + (lane >> 2) + ((j >> 1) << 3);
                int n = wn * 16 + nf * 8 + ((lane & 3) << 1) + (j & 1);
                sA[m * DD + n] = acc2[mi][nf][j] + s_b2[n];
            }
    __syncthreads();
    {
        const int cc = tid & 31;
        const int r0 = tid >> 5;
#pragma unroll
        for (int it = 0; it < 8; it++) {
            int r = r0 + it * 16;
            float4 v = *(const float4*)(sA + r * DD + cc * 4);
            float* hp = h + (size_t)(n0 + r) * DD + cc * 4;
            float4 o = *(float4*)hp;
            o.x += v.x; o.y += v.y; o.z += v.z; o.w += v.w;
            *(float4*)hp = o;
        }
    }
}

// ---------------- per-graph counts ------------------------------------------
__global__ void cnt_k(const int* __restrict__ batch, float* __restrict__ cnt)
{
    int n = blockIdx.x * blockDim.x + threadIdx.x;
    if (n < NN) atomicAdd(&cnt[batch[n]], 1.0f);
}

// ---------------- per-graph feature sums ------------------------------------
__global__ void __launch_bounds__(128) gsum_k(
    const float* __restrict__ h, const int* __restrict__ batch,
    float* __restrict__ gsum)
{
    const int j = threadIdx.x;
    const int n0 = blockIdx.x * 32;
    int curb = batch[n0];
    float acc = 0.0f;
    for (int i = 0; i < 32; i++) {
        int n = n0 + i;
        int b = batch[n];
        if (b != curb) {
            atomicAdd(&gsum[curb * DD + j], acc);
            acc = 0.0f;
            curb = b;
        }
        acc += h[n * DD + j];
    }
    atomicAdd(&gsum[curb * DD + j], acc);
}

// ---------------- readout MLP (single block) --------------------------------
__global__ void __launch_bounds__(256) final_k(
    const float* __restrict__ gsum, const float* __restrict__ cnt,
    const float* __restrict__ W1, const float* __restrict__ b1,
    const float* __restrict__ W2, const float* __restrict__ b2,
    float* __restrict__ out)
{
    __shared__ float sg[BB * DD];
    __shared__ float sh[BB * HH];
    const int tid = threadIdx.x;

    for (int idx = tid; idx < BB * DD; idx += 256) {
        int b = idx >> 7;
        sg[idx] = gsum[idx] / fmaxf(cnt[b], 1.0f);
    }
    __syncthreads();

    {
        const int j = tid;
        float acc[BB];
#pragma unroll
        for (int b = 0; b < BB; b++) acc[b] = 0.0f;
        for (int k = 0; k < DD; k++) {
            float w = W1[k * HH + j];
#pragma unroll
            for (int b = 0; b < BB; b++) acc[b] = fmaf(sg[b * DD + k], w, acc[b]);
        }
        float bb = b1[j];
#pragma unroll
        for (int b = 0; b < BB; b++) sh[b * HH + j] = silu_f(acc[b] + bb);
    }
    __syncthreads();

    if (tid < OUTD) {
        const int j = tid;
        float acc[BB];
#pragma unroll
        for (int b = 0; b < BB; b++) acc[b] = 0.0f;
        for (int k = 0; k < HH; k++) {
            float w = W2[k * OUTD + j];
#pragma unroll
            for (int b = 0; b < BB; b++) acc[b] = fmaf(sh[b * HH + k], w, acc[b]);
        }
        float bb = b2[j];
#pragma unroll
        for (int b = 0; b < BB; b++) out[b * OUTD + j] = acc[b] + bb;
    }
}

// ---------------- launch -----------------------------------------------------
#define SMEM_MSG (8 * KC1 * 32 * 4 * 4)   // 147456 bytes
#define SMEM_UPD (8 * 32 * 32 * 4 * 4)    // 131072 bytes

extern "C" void kernel_launch(void* const* d_in, const int* in_sizes, int n_in,
                              void* d_out, int out_size)
{
    const float* pos    = (const float*)d_in[0];
    const float* nf     = (const float*)d_in[1];
    const int*   EI     = (const int*)d_in[2];
    const int*   batch  = (const int*)d_in[3];
    const float* emb_W1 = (const float*)d_in[4];
    const float* emb_b1 = (const float*)d_in[5];
    const float* emb_W2 = (const float*)d_in[6];
    const float* emb_b2 = (const float*)d_in[7];
    const float* msg_W1 = (const float*)d_in[8];
    const float* msg_b1 = (const float*)d_in[9];
    const float* msg_W2 = (const float*)d_in[10];
    const float* msg_b2 = (const float*)d_in[11];
    const float* upd_W1 = (const float*)d_in[12];
    const float* upd_b1 = (const float*)d_in[13];
    const float* upd_W2 = (const float*)d_in[14];
    const float* upd_b2 = (const float*)d_in[15];
    const float* r_W1   = (const float*)d_in[16];
    const float* r_b1   = (const float*)d_in[17];
    const float* r_W2   = (const float*)d_in[18];
    const float* r_b2   = (const float*)d_in[19];
    float* out = (float*)d_out;

    void *p_h, *p_agg, *p_ef, *p_gsum, *p_gcnt, *p_w1f, *p_w2f, *p_wu1f, *p_wu2f;
    cudaGetSymbolAddress(&p_h, g_h);
    cudaGetSymbolAddress(&p_agg, g_agg);
    cudaGetSymbolAddress(&p_ef, g_ef);
    cudaGetSymbolAddress(&p_gsum, g_gsum);
    cudaGetSymbolAddress(&p_gcnt, g_gcnt);
    cudaGetSymbolAddress(&p_w1f, g_W1f);
    cudaGetSymbolAddress(&p_w2f, g_W2f);
    cudaGetSymbolAddress(&p_wu1f, g_WU1f);
    cudaGetSymbolAddress(&p_wu2f, g_WU2f);
    float* h    = (float*)p_h;
    float* agg  = (float*)p_agg;
    float* ef   = (float*)p_ef;
    float* gsum = (float*)p_gsum;
    float* gcnt = (float*)p_gcnt;
    float* W1f  = (float*)p_w1f;
    float* W2f  = (float*)p_w2f;
    float* WU1f = (float*)p_wu1f;
    float* WU2f = (float*)p_wu2f;

    cudaFuncSetAttribute(msg_mma_k, cudaFuncAttributeMaxDynamicSharedMemorySize, SMEM_MSG);
    cudaFuncSetAttribute(upd_mma_k, cudaFuncAttributeMaxDynamicSharedMemorySize, SMEM_UPD);

    prep1_k<<<(NL * KC1 * 16 * 32 * 4 + 255) / 256, 256>>>(msg_W1, W1f);
    prep2_k<<<(NL * KC2 * 8 * 32 * 4 + 255) / 256, 256>>>(msg_W2, W2f);
    prepU1_k<<<(NL * 32 * 16 * 32 * 4 + 255) / 256, 256>>>(upd_W1, WU1f);
    prepU2_k<<<(NL * 32 * 8 * 32 * 4 + 255) / 256, 256>>>(upd_W2, WU2f);
    embed_k<<<NN / 16, 128>>>(nf, emb_W1, emb_b1, emb_W2, emb_b2, h);
    rbf_k<<<EE / 256, 256>>>(pos, EI, ef);

    for (int l = 0; l < NL; l++) {
        cudaMemsetAsync(agg, 0, (size_t)NN * DD * sizeof(float), 0);
        msg_mma_k<<<EE / 128, 512, SMEM_MSG>>>(
            EI, h, ef,
            W1f + (size_t)l * KC1 * 16 * 32 * 4,
            msg_b1 + (size_t)l * HH,
            W2f + (size_t)l * KC2 * 8 * 32 * 4,
            msg_b2 + (size_t)l * DD,
            agg);
        upd_mma_k<<<NN / 128, 512, SMEM_UPD>>>(
            h, agg,
            WU1f + (size_t)l * 32 * 16 * 32 * 4,
            upd_b1 + (size_t)l * HH,
            WU2f + (size_t)l * 32 * 8 * 32 * 4,
            upd_b2 + (size_t)l * DD);
    }

    cudaMemsetAsync(gsum, 0, (size_t)BB * DD * sizeof(float), 0);
    cudaMemsetAsync(gcnt, 0, (size_t)BB * sizeof(float), 0);
    cnt_k<<<NN / 256, 256>>>(batch, gcnt);
    gsum_k<<<NN / 32, 128>>>(h, batch, gsum);
    final_k<<<1, 256>>>(gsum, gcnt, r_W1, r_b1, r_W2, r_b2, out);
}

// round 8
// speedup vs baseline: 6.2544x; 1.7040x over previous
#include <cuda_runtime.h>
#include <cuda_fp16.h>
#include <math.h>
#include <stdint.h>

#define NN    16384
#define EE    524288
#define BB    8
#define FIN   26
#define DD    128
#define HH    256
#define OUTD  64
#define NL    4
#define NRBF  16
#define KIN   272          // 2*DD + NRBF
#define KC1H  18           // msg GEMM1 k-chunks of 16 (K padded to 288)
#define KC2H  16           // msg GEMM2 / upd k-chunks of 16 (K = 256)

// ---------------- scratch (device globals; no allocation allowed) ----------
__device__ float g_h[NN * DD];
__device__ float g_agg[NN * DD];
__device__ float g_ef[EE * NRBF];
__device__ float g_gsum[BB * DD];
__device__ float g_gcnt[BB];
// weights in fp16 B-fragment layout (packed half2 per uint)
__device__ unsigned int g_W1f[NL * KC1H * 16 * 32 * 4];   // msg GEMM1 [l][kc][np16][t32][i4]
__device__ unsigned int g_W2f[NL * KC2H * 8 * 32 * 4];    // msg GEMM2 [l][kc][np8][t32][i4]
__device__ unsigned int g_WU1f[NL * 16 * 16 * 32 * 4];    // upd GEMM1 K=256,N=256
__device__ unsigned int g_WU2f[NL * 16 * 8 * 32 * 4];     // upd GEMM2 K=256,N=128

__device__ __forceinline__ float silu_f(float x) {
    return x * (1.0f / (1.0f + __expf(-x)));
}
__device__ __forceinline__ unsigned int packh2(float a, float b) {
    __half2 h = __floats2half2_rn(a, b);
    return *reinterpret_cast<unsigned int*>(&h);
}

// fp16 m16n8k16 MMA (baseline PTX, valid on compute_103)
__device__ __forceinline__ void mma16(float* c, uint4 a, uint32_t b0, uint32_t b1) {
    asm volatile(
        "mma.sync.aligned.m16n8k16.row.col.f32.f16.f16.f32 "
        "{%0,%1,%2,%3}, {%4,%5,%6,%7}, {%8,%9}, {%0,%1,%2,%3};"
        : "+f"(c[0]), "+f"(c[1]), "+f"(c[2]), "+f"(c[3])
        : "r"(a.x), "r"(a.y), "r"(a.z), "r"(a.w), "r"(b0), "r"(b1));
}

__device__ __forceinline__ void red4(float* p, float4 v) {
    asm volatile("red.global.add.v4.f32 [%0], {%1,%2,%3,%4};"
                 :: "l"(p), "f"(v.x), "f"(v.y), "f"(v.z), "f"(v.w) : "memory");
}

// ---------------- weight prep: fp16 fragment layout --------------------------
// B-frag m16n8k16 (col-major B, shape k16 x n8):
//   b0: n = t/4, k = (t%4)*2 + {0,1};  b1: n = t/4, k = 8 + (t%4)*2 + {0,1}
// uint4 per (kc,np,t): i=0,1 -> n-frag np*2 (b0,b1); i=2,3 -> n-frag np*2+1
__global__ void prep1_k(const float* __restrict__ W1, unsigned int* __restrict__ Wf) {
    int idx = blockIdx.x * 256 + threadIdx.x;
    const int PER = KC1H * 16 * 32 * 4;
    if (idx >= NL * PER) return;
    int l = idx / PER, r = idx - l * PER;
    int kc = r / 2048;  r -= kc * 2048;
    int np = r / 128;   r -= np * 128;
    int t = r / 4, i = r & 3;
    int k0 = kc * 16 + (t & 3) * 2 + 8 * (i & 1);
    int n = np * 16 + ((i >> 1) << 3) + (t >> 2);
    float v0 = (k0 < KIN)     ? W1[((size_t)l * KIN + k0) * HH + n]     : 0.0f;
    float v1 = (k0 + 1 < KIN) ? W1[((size_t)l * KIN + k0 + 1) * HH + n] : 0.0f;
    Wf[idx] = packh2(v0, v1);
}
__global__ void prep2_k(const float* __restrict__ W2, unsigned int* __restrict__ Wf) {
    int idx = blockIdx.x * 256 + threadIdx.x;
    const int PER = KC2H * 8 * 32 * 4;
    if (idx >= NL * PER) return;
    int l = idx / PER, r = idx - l * PER;
    int kc = r / 1024;  r -= kc * 1024;
    int np = r / 128;   r -= np * 128;
    int t = r / 4, i = r & 3;
    int k0 = kc * 16 + (t & 3) * 2 + 8 * (i & 1);
    int n = np * 16 + ((i >> 1) << 3) + (t >> 2);
    Wf[idx] = packh2(W2[((size_t)l * HH + k0) * DD + n],
                     W2[((size_t)l * HH + k0 + 1) * DD + n]);
}
__global__ void prepU1_k(const float* __restrict__ W1, unsigned int* __restrict__ Wf) {
    int idx = blockIdx.x * 256 + threadIdx.x;
    const int PER = 16 * 16 * 32 * 4;
    if (idx >= NL * PER) return;
    int l = idx / PER, r = idx - l * PER;
    int kc = r / 2048;  r -= kc * 2048;
    int np = r / 128;   r -= np * 128;
    int t = r / 4, i = r & 3;
    int k0 = kc * 16 + (t & 3) * 2 + 8 * (i & 1);
    int n = np * 16 + ((i >> 1) << 3) + (t >> 2);
    Wf[idx] = packh2(W1[((size_t)l * 256 + k0) * HH + n],
                     W1[((size_t)l * 256 + k0 + 1) * HH + n]);
}
__global__ void prepU2_k(const float* __restrict__ W2, unsigned int* __restrict__ Wf) {
    int idx = blockIdx.x * 256 + threadIdx.x;
    const int PER = 16 * 8 * 32 * 4;
    if (idx >= NL * PER) return;
    int l = idx / PER, r = idx - l * PER;
    int kc = r / 1024;  r -= kc * 1024;
    int np = r / 128;   r -= np * 128;
    int t = r / 4, i = r & 3;
    int k0 = kc * 16 + (t & 3) * 2 + 8 * (i & 1);
    int n = np * 16 + ((i >> 1) << 3) + (t >> 2);
    Wf[idx] = packh2(W2[((size_t)l * HH + k0) * DD + n],
                     W2[((size_t)l * HH + k0 + 1) * DD + n]);
}

// ---------------- node embedding: (N,26) -> silu -> (N,128), fp32 ------------
__global__ void __launch_bounds__(128) embed_k(
    const float* __restrict__ nf,
    const float* __restrict__ W1, const float* __restrict__ b1,
    const float* __restrict__ W2, const float* __restrict__ b2,
    float* __restrict__ h)
{
    __shared__ __align__(16) float s_in[16 * FIN];
    __shared__ __align__(16) float s_hid[16 * DD];
    const int tid = threadIdx.x;
    const int n0 = blockIdx.x * 16;

    for (int idx = tid; idx < 16 * FIN; idx += 128) {
        int e = idx / FIN, k = idx - e * FIN;
        s_in[idx] = nf[(n0 + e) * FIN + k];
    }
    __syncthreads();

    const int j = tid;
    float acc[16];
#pragma unroll
    for (int e = 0; e < 16; e++) acc[e] = 0.0f;
    for (int k = 0; k < FIN; k++) {
        float w = W1[k * DD + j];
#pragma unroll
        for (int e = 0; e < 16; e++) acc[e] = fmaf(s_in[e * FIN + k], w, acc[e]);
    }
    float bb1 = b1[j];
#pragma unroll
    for (int e = 0; e < 16; e++) s_hid[e * DD + j] = silu_f(acc[e] + bb1);
    __syncthreads();

    float acc2[16];
#pragma unroll
    for (int e = 0; e < 16; e++) acc2[e] = 0.0f;
    const float4* sh4 = (const float4*)s_hid;
    for (int k4 = 0; k4 < DD / 4; k4++) {
        const float* wp = &W2[(k4 * 4) * DD + j];
        float w0 = wp[0], w1 = wp[DD], w2 = wp[2 * DD], w3 = wp[3 * DD];
#pragma unroll
        for (int e = 0; e < 16; e++) {
            float4 a = sh4[e * (DD / 4) + k4];
            acc2[e] = fmaf(a.x, w0, acc2[e]);
            acc2[e] = fmaf(a.y, w1, acc2[e]);
            acc2[e] = fmaf(a.z, w2, acc2[e]);
            acc2[e] = fmaf(a.w, w3, acc2[e]);
        }
    }
    float bb2 = b2[j];
#pragma unroll
    for (int e = 0; e < 16; e++) h[(n0 + e) * DD + j] = acc2[e] + bb2;
}

// ---------------- per-edge RBF features (E,16) -------------------------------
__global__ void rbf_k(const float* __restrict__ pos, const int* __restrict__ EI,
                      float* __restrict__ ef)
{
    int e = blockIdx.x * blockDim.x + threadIdx.x;
    if (e >= EE) return;
    int s = EI[e];
    int d = EI[EE + e];
    float dx = pos[d * 3 + 0] - pos[s * 3 + 0];
    float dy = pos[d * 3 + 1] - pos[s * 3 + 1];
    float dz = pos[d * 3 + 2] - pos[s * 3 + 2];
    float dist = sqrtf(dx * dx + dy * dy + dz * dz + 1e-12f);
    float env = (dist < 10.0f)
                    ? 0.5f * (cosf(3.14159265358979323846f * dist * 0.1f) + 1.0f)
                    : 0.0f;
    const float inv2w2 = 1.0f / (2.0f * 0.625f * 0.625f);
#pragma unroll
    for (int k = 0; k < NRBF; k++) {
        float c = (10.0f / 15.0f) * (float)k;
        float t = dist - c;
        ef[e * NRBF + k] = __expf(-t * t * inv2w2) * env;
    }
}

// ---------------- fp16 A-fragment staging helper -----------------------------
// A-frag m16n8k16 (row-major 16x16): within chunk, element (r,c):
//   t = (r%8)*4 + ((c%8)>>1); i = (r>>3) + 2*(c>=8); half = c&1
__device__ __forceinline__ void stage_f4(unsigned int* sAu, int KC, int mt, int r,
                                         int k0, float4 v) {
    int kc = k0 >> 4;
    int c0 = k0 & 15;
    int t0 = ((r & 7) << 2) + ((c0 & 7) >> 1);
    int ii = (r >> 3) + ((c0 & 8) ? 2 : 0);
    unsigned int* base = sAu + ((mt * KC + kc) * 32) * 4 + ii;
    base[t0 * 4]       = packh2(v.x, v.y);
    base[(t0 + 1) * 4] = packh2(v.z, v.w);
}

// ---------------- tensor-core (fp16 mma) message MLP + v4-red scatter --------
// CTA: 128 edges, 512 threads = 16 warps (2M x 8N).
__global__ void __launch_bounds__(512, 1) msg_mma_k(
    const int* __restrict__ EI,
    const float* __restrict__ h, const float* __restrict__ ef,
    const unsigned int* __restrict__ W1f, const float* __restrict__ b1,
    const unsigned int* __restrict__ W2f, const float* __restrict__ b2,
    float* __restrict__ agg)
{
    extern __shared__ __align__(16) unsigned int sAu[];   // 73728 B (KC1H layout)
    float* sAf = (float*)sAu;
    __shared__ float s_b1[HH];
    __shared__ float s_b2[DD];
    __shared__ int   s_dst[128];

    const int tid = threadIdx.x;
    const int e0 = blockIdx.x * 128;

    if (tid < HH) s_b1[tid] = b1[tid];
    if (tid < DD) s_b2[tid] = b2[tid];
    if (tid < 128) s_dst[tid] = EI[EE + e0 + tid];

    // ---- stage gathered edge features into fp16 A-fragment layout ----
    {
        const int e = tid >> 2;
        const int q = tid & 3;
        const int src = EI[e0 + e];
        const int dst = EI[EE + e0 + e];
        const float* hs = h + (size_t)src * DD;
        const float* hd = h + (size_t)dst * DD;
        const float* ep = ef + (size_t)(e0 + e) * NRBF;
        const int r = e & 15, mt = e >> 4;
#pragma unroll
        for (int j = 0; j < 18; j++) {
            int k0 = j * 16 + q * 4;
            float4 v;
            if (k0 < 128)       v = *(const float4*)(hs + k0);
            else if (k0 < 256)  v = *(const float4*)(hd + (k0 - 128));
            else if (k0 < 272)  v = *(const float4*)(ep + (k0 - 256));
            else                v = make_float4(0.f, 0.f, 0.f, 0.f);
            stage_f4(sAu, KC1H, mt, r, k0, v);
        }
    }
    __syncthreads();

    const int wid = tid >> 5, lane = tid & 31;
    const int wm = wid >> 3, wn = wid & 7;   // 2 M-tiles(64) x 8 N-tiles(32)

    // ================= GEMM1: M-tile 64 (4 mfrags), N-tile 32 (2 npairs) ====
    float acc[4][4][4];
#pragma unroll
    for (int a = 0; a < 4; a++)
#pragma unroll
        for (int b = 0; b < 4; b++)
#pragma unroll
            for (int c = 0; c < 4; c++) acc[a][b][c] = 0.0f;
    {
        const uint4* ap0 = (const uint4*)sAu + (wm * 4 + 0) * KC1H * 32 + lane;
        const uint4* ap1 = (const uint4*)sAu + (wm * 4 + 1) * KC1H * 32 + lane;
        const uint4* ap2 = (const uint4*)sAu + (wm * 4 + 2) * KC1H * 32 + lane;
        const uint4* ap3 = (const uint4*)sAu + (wm * 4 + 3) * KC1H * 32 + lane;
        const uint4* bp = (const uint4*)W1f + (wn * 2) * 32 + lane;
#pragma unroll 2
        for (int kc = 0; kc < KC1H; kc++) {
            uint4 b0 = bp[kc * 512];
            uint4 b1v = bp[kc * 512 + 32];
            uint4 a0 = ap0[kc * 32], a1 = ap1[kc * 32];
            uint4 a2 = ap2[kc * 32], a3 = ap3[kc * 32];
            mma16(acc[0][0], a0, b0.x, b0.y);  mma16(acc[0][1], a0, b0.z, b0.w);
            mma16(acc[0][2], a0, b1v.x, b1v.y); mma16(acc[0][3], a0, b1v.z, b1v.w);
            mma16(acc[1][0], a1, b0.x, b0.y);  mma16(acc[1][1], a1, b0.z, b0.w);
            mma16(acc[1][2], a1, b1v.x, b1v.y); mma16(acc[1][3], a1, b1v.z, b1v.w);
            mma16(acc[2][0], a2, b0.x, b0.y);  mma16(acc[2][1], a2, b0.z, b0.w);
            mma16(acc[2][2], a2, b1v.x, b1v.y); mma16(acc[2][3], a2, b1v.z, b1v.w);
            mma16(acc[3][0], a3, b0.x, b0.y);  mma16(acc[3][1], a3, b0.z, b0.w);
            mma16(acc[3][2], a3, b1v.x, b1v.y); mma16(acc[3][3], a3, b1v.z, b1v.w);
        }
    }
    __syncthreads();

    // ---- epilogue1: bias + silu -> A2 fp16 fragment layout (KC2H) ----
#pragma unroll
    for (int mi = 0; mi < 4; mi++)
#pragma unroll
        for (int nf = 0; nf < 4; nf++) {
            int m_lo = wm * 64 + mi * 16 + (lane >> 2);
            int n = wn * 32 + nf * 8 + ((lane & 3) << 1);
            float y00 = silu_f(acc[mi][nf][0] + s_b1[n]);
            float y01 = silu_f(acc[mi][nf][1] + s_b1[n + 1]);
            float y10 = silu_f(acc[mi][nf][2] + s_b1[n]);
            float y11 = silu_f(acc[mi][nf][3] + s_b1[n + 1]);
            int mt2 = m_lo >> 4;
            int kc2 = n >> 4, c2 = n & 15;
            int t2 = ((m_lo & 7) << 2) + ((c2 & 7) >> 1);
            int ib = (c2 & 8) ? 2 : 0;
            unsigned int* base = sAu + ((mt2 * KC2H + kc2) * 32 + t2) * 4 + ib;
            base[0] = packh2(y00, y01);
            base[1] = packh2(y10, y11);
        }
    __syncthreads();

    // ================= GEMM2: M-tile 64, N-tile 16 (1 npair) ================
    float acc2[4][2][4];
#pragma unroll
    for (int a = 0; a < 4; a++)
#pragma unroll
        for (int b = 0; b < 2; b++)
#pragma unroll
            for (int c = 0; c < 4; c++) acc2[a][b][c] = 0.0f;
    {
        const uint4* ap0 = (const uint4*)sAu + (wm * 4 + 0) * KC2H * 32 + lane;
        const uint4* ap1 = (const uint4*)sAu + (wm * 4 + 1) * KC2H * 32 + lane;
        const uint4* ap2 = (const uint4*)sAu + (wm * 4 + 2) * KC2H * 32 + lane;
        const uint4* ap3 = (const uint4*)sAu + (wm * 4 + 3) * KC2H * 32 + lane;
        const uint4* bp = (const uint4*)W2f + wn * 32 + lane;
#pragma unroll 2
        for (int kc = 0; kc < KC2H; kc++) {
            uint4 b = bp[kc * 256];
            uint4 a0 = ap0[kc * 32], a1 = ap1[kc * 32];
            uint4 a2 = ap2[kc * 32], a3 = ap3[kc * 32];
            mma16(acc2[0][0], a0, b.x, b.y);  mma16(acc2[0][1], a0, b.z, b.w);
            mma16(acc2[1][0], a1, b.x, b.y);  mma16(acc2[1][1], a1, b.z, b.w);
            mma16(acc2[2][0], a2, b.x, b.y);  mma16(acc2[2][1], a2, b.z, b.w);
            mma16(acc2[3][0], a3, b.x, b.y);  mma16(acc2[3][1], a3, b.z, b.w);
        }
    }
    __syncthreads();   // sA free -> reuse as fp32 D2 staging [128][128]

    // ---- epilogue2: stage D2+bias, then red.v4 scatter ----
#pragma unroll
    for (int mi = 0; mi < 4; mi++)
#pragma unroll
        for (int nf = 0; nf < 2; nf++)
#pragma unroll
            for (int j = 0; j < 4; j++) {
                int m = wm * 64 + mi * 16 + (lane >> 2) + ((j >> 1) << 3);
                int n = wn * 16 + nf * 8 + ((lane & 3) << 1) + (j & 1);
                sAf[m * DD + n] = acc2[mi][nf][j] + s_b2[n];
            }
    __syncthreads();
    {
        const int cc = tid & 31;
        const int r0 = tid >> 5;
#pragma unroll
        for (int it = 0; it < 8; it++) {
            int r = r0 + it * 16;
            float4 v = *(const float4*)(sAf + r * DD + cc * 4);
            red4(agg + (size_t)s_dst[r] * DD + cc * 4, v);
        }
    }
}

// ---------------- fp16 tensor-core update MLP (residual, no atomics) ---------
// CTA: 128 nodes, 512 threads = 16 warps (2M x 8N). K=256 both GEMMs.
__global__ void __launch_bounds__(512, 1) upd_mma_k(
    float* __restrict__ h, const float* __restrict__ agg,
    const unsigned int* __restrict__ W1f, const float* __restrict__ b1,
    const unsigned int* __restrict__ W2f, const float* __restrict__ b2)
{
    extern __shared__ __align__(16) unsigned int sAu[];   // 65536 B
    float* sAf = (float*)sAu;
    __shared__ float s_b1[HH];
    __shared__ float s_b2[DD];

    const int tid = threadIdx.x;
    const int n0 = blockIdx.x * 128;

    if (tid < HH) s_b1[tid] = b1[tid];
    if (tid < DD) s_b2[tid] = b2[tid];

    // ---- stage [h | agg] into fp16 A-fragment layout (KC=16) ----
    {
        const int e = tid >> 2;
        const int q = tid & 3;
        const float* hs = h + (size_t)(n0 + e) * DD;
        const float* ag = agg + (size_t)(n0 + e) * DD;
        const int r = e & 15, mt = e >> 4;
#pragma unroll
        for (int j = 0; j < 16; j++) {
            int k0 = j * 16 + q * 4;
            float4 v = (k0 < 128) ? *(const float4*)(hs + k0)
                                  : *(const float4*)(ag + (k0 - 128));
            stage_f4(sAu, 16, mt, r, k0, v);
        }
    }
    __syncthreads();

    const int wid = tid >> 5, lane = tid & 31;
    const int wm = wid >> 3, wn = wid & 7;

    // GEMM1 (K=256, N=256)
    float acc[4][4][4];
#pragma unroll
    for (int a = 0; a < 4; a++)
#pragma unroll
        for (int b = 0; b < 4; b++)
#pragma unroll
            for (int c = 0; c < 4; c++) acc[a][b][c] = 0.0f;
    {
        const uint4* ap0 = (const uint4*)sAu + (wm * 4 + 0) * 16 * 32 + lane;
        const uint4* ap1 = (const uint4*)sAu + (wm * 4 + 1) * 16 * 32 + lane;
        const uint4* ap2 = (const uint4*)sAu + (wm * 4 + 2) * 16 * 32 + lane;
        const uint4* ap3 = (const uint4*)sAu + (wm * 4 + 3) * 16 * 32 + lane;
        const uint4* bp = (const uint4*)W1f + (wn * 2) * 32 + lane;
#pragma unroll 2
        for (int kc = 0; kc < 16; kc++) {
            uint4 b0 = bp[kc * 512];
            uint4 b1v = bp[kc * 512 + 32];
            uint4 a0 = ap0[kc * 32], a1 = ap1[kc * 32];
            uint4 a2 = ap2[kc * 32], a3 = ap3[kc * 32];
            mma16(acc[0][0], a0, b0.x, b0.y);  mma16(acc[0][1], a0, b0.z, b0.w);
            mma16(acc[0][2], a0, b1v.x, b1v.y); mma16(acc[0][3], a0, b1v.z, b1v.w);
            mma16(acc[1][0], a1, b0.x, b0.y);  mma16(acc[1][1], a1, b0.z, b0.w);
            mma16(acc[1][2], a1, b1v.x, b1v.y); mma16(acc[1][3], a1, b1v.z, b1v.w);
            mma16(acc[2][0], a2, b0.x, b0.y);  mma16(acc[2][1], a2, b0.z, b0.w);
            mma16(acc[2][2], a2, b1v.x, b1v.y); mma16(acc[2][3], a2, b1v.z, b1v.w);
            mma16(acc[3][0], a3, b0.x, b0.y);  mma16(acc[3][1], a3, b0.z, b0.w);
            mma16(acc[3][2], a3, b1v.x, b1v.y); mma16(acc[3][3], a3, b1v.z, b1v.w);
        }
    }
    __syncthreads();

#pragma unroll
    for (int mi = 0; mi < 4; mi++)
#pragma unroll
        for (int nf = 0; nf < 4; nf++) {
            int m_lo = wm * 64 + mi * 16 + (lane >> 2);
            int n = wn * 32 + nf * 8 + ((lane & 3) << 1);
            float y00 = silu_f(acc[mi][nf][0] + s_b1[n]);
            float y01 = silu_f(acc[mi][nf][1] + s_b1[n + 1]);
            float y10 = silu_f(acc[mi][nf][2] + s_b1[n]);
            float y11 = silu_f(acc[mi][nf][3] + s_b1[n + 1]);
            int mt2 = m_lo >> 4;
            int kc2 = n >> 4, c2 = n & 15;
            int t2 = ((m_lo & 7) << 2) + ((c2 & 7) >> 1);
            int ib = (c2 & 8) ? 2 : 0;
            unsigned int* base = sAu + ((mt2 * 16 + kc2) * 32 + t2) * 4 + ib;
            base[0] = packh2(y00, y01);
            base[1] = packh2(y10, y11);
        }
    __syncthreads();

    // GEMM2 (K=256, N=128)
    float acc2[4][2][4];
#pragma unroll
    for (int a = 0; a < 4; a++)
#pragma unroll
        for (int b = 0; b < 2; b++)
#pragma unroll
            for (int c = 0; c < 4; c++) acc2[a][b][c] = 0.0f;
    {
        const uint4* ap0 = (const uint4*)sAu + (wm * 4 + 0) * 16 * 32 + lane;
        const uint4* ap1 = (const uint4*)sAu + (wm * 4 + 1) * 16 * 32 + lane;
        const uint4* ap2 = (const uint4*)sAu + (wm * 4 + 2) * 16 * 32 + lane;
        const uint4* ap3 = (const uint4*)sAu + (wm * 4 + 3) * 16 * 32 + lane;
        const uint4* bp = (const uint4*)W2f + wn * 32 + lane;
#pragma unroll 2
        for (int kc = 0; kc < 16; kc++) {
            uint4 b = bp[kc * 256];
            uint4 a0 = ap0[kc * 32], a1 = ap1[kc * 32];
            uint4 a2 = ap2[kc * 32], a3 = ap3[kc * 32];
            mma16(acc2[0][0], a0, b.x, b.y);  mma16(acc2[0][1], a0, b.z, b.w);
            mma16(acc2[1][0], a1, b.x, b.y);  mma16(acc2[1][1], a1, b.z, b.w);
            mma16(acc2[2][0], a2, b.x, b.y);  mma16(acc2[2][1], a2, b.z, b.w);
            mma16(acc2[3][0], a3, b.x, b.y);  mma16(acc2[3][1], a3, b.z, b.w);
        }
    }
    __syncthreads();

    // stage D2+bias, then coalesced residual add
#pragma unroll
    for (int mi = 0; mi < 4; mi++)
#pragma unroll
        for (int nf = 0; nf < 2; nf++)
#pragma unroll
            for (int j = 0; j < 4; j++) {
                int m = wm * 64 + mi * 16 + (lane >> 2) + ((j >> 1) << 3);
                int n = wn * 16 + nf * 8 + ((lane & 3) << 1) + (j & 1);
                sAf[m * DD + n] = acc2[mi][nf][j] + s_b2[n];
            }
    __syncthreads();
    {
        const int cc = tid & 31;
        const int r0 = tid >> 5;
#pragma unroll
        for (int it = 0; it < 8; it++) {
            int r = r0 + it * 16;
            float4 v = *(const float4*)(sAf + r * DD + cc * 4);
            float* hp = h + (size_t)(n0 + r) * DD + cc * 4;
            float4 o = *(float4*)hp;
            o.x += v.x; o.y += v.y; o.z += v.z; o.w += v.w;
            *(float4*)hp = o;
        }
    }
}

// ---------------- per-graph counts ------------------------------------------
__global__ void cnt_k(const int* __restrict__ batch, float* __restrict__ cnt)
{
    int n = blockIdx.x * blockDim.x + threadIdx.x;
    if (n < NN) atomicAdd(&cnt[batch[n]], 1.0f);
}

// ---------------- per-graph feature sums ------------------------------------
__global__ void __launch_bounds__(128) gsum_k(
    const float* __restrict__ h, const int* __restrict__ batch,
    float* __restrict__ gsum)
{
    const int j = threadIdx.x;
    const int n0 = blockIdx.x * 32;
    int curb = batch[n0];
    float acc = 0.0f;
    for (int i = 0; i < 32; i++) {
        int n = n0 + i;
        int b = batch[n];
        if (b != curb) {
            atomicAdd(&gsum[curb * DD + j], acc);
            acc = 0.0f;
            curb = b;
        }
        acc += h[n * DD + j];
    }
    atomicAdd(&gsum[curb * DD + j], acc);
}

// ---------------- readout MLP (single block) --------------------------------
__global__ void __launch_bounds__(256) final_k(
    const float* __restrict__ gsum, const float* __restrict__ cnt,
    const float* __restrict__ W1, const float* __restrict__ b1,
    const float* __restrict__ W2, const float* __restrict__ b2,
    float* __restrict__ out)
{
    __shared__ float sg[BB * DD];
    __shared__ float sh[BB * HH];
    const int tid = threadIdx.x;

    for (int idx = tid; idx < BB * DD; idx += 256) {
        int b = idx >> 7;
        sg[idx] = gsum[idx] / fmaxf(cnt[b], 1.0f);
    }
    __syncthreads();

    {
        const int j = tid;
        float acc[BB];
#pragma unroll
        for (int b = 0; b < BB; b++) acc[b] = 0.0f;
        for (int k = 0; k < DD; k++) {
            float w = W1[k * HH + j];
#pragma unroll
            for (int b = 0; b < BB; b++) acc[b] = fmaf(sg[b * DD + k], w, acc[b]);
        }
        float bb = b1[j];
#pragma unroll
        for (int b = 0; b < BB; b++) sh[b * HH + j] = silu_f(acc[b] + bb);
    }
    __syncthreads();

    if (tid < OUTD) {
        const int j = tid;
        float acc[BB];
#pragma unroll
        for (int b = 0; b < BB; b++) acc[b] = 0.0f;
        for (int k = 0; k < HH; k++) {
            float w = W2[k * OUTD + j];
#pragma unroll
            for (int b = 0; b < BB; b++) acc[b] = fmaf(sh[b * HH + k], w, acc[b]);
        }
        float bb = b2[j];
#pragma unroll
        for (int b = 0; b < BB; b++) out[b * OUTD + j] = acc[b] + bb;
    }
}

// ---------------- launch -----------------------------------------------------
#define SMEM_MSG (8 * KC1H * 32 * 4 * 4)   // 73728 bytes (also >= 64KB D2 staging)
#define SMEM_UPD (8 * 16 * 32 * 4 * 4)     // 65536 bytes

extern "C" void kernel_launch(void* const* d_in, const int* in_sizes, int n_in,
                              void* d_out, int out_size)
{
    const float* pos    = (const float*)d_in[0];
    const float* nf     = (const float*)d_in[1];
    const int*   EI     = (const int*)d_in[2];
    const int*   batch  = (const int*)d_in[3];
    const float* emb_W1 = (const float*)d_in[4];
    const float* emb_b1 = (const float*)d_in[5];
    const float* emb_W2 = (const float*)d_in[6];
    const float* emb_b2 = (const float*)d_in[7];
    const float* msg_W1 = (const float*)d_in[8];
    const float* msg_b1 = (const float*)d_in[9];
    const float* msg_W2 = (const float*)d_in[10];
    const float* msg_b2 = (const float*)d_in[11];
    const float* upd_W1 = (const float*)d_in[12];
    const float* upd_b1 = (const float*)d_in[13];
    const float* upd_W2 = (const float*)d_in[14];
    const float* upd_b2 = (const float*)d_in[15];
    const float* r_W1   = (const float*)d_in[16];
    const float* r_b1   = (const float*)d_in[17];
    const float* r_W2   = (const float*)d_in[18];
    const float* r_b2   = (const float*)d_in[19];
    float* out = (float*)d_out;

    void *p_h, *p_agg, *p_ef, *p_gsum, *p_gcnt, *p_w1f, *p_w2f, *p_wu1f, *p_wu2f;
    cudaGetSymbolAddress(&p_h, g_h);
    cudaGetSymbolAddress(&p_agg, g_agg);
    cudaGetSymbolAddress(&p_ef, g_ef);
    cudaGetSymbolAddress(&p_gsum, g_gsum);
    cudaGetSymbolAddress(&p_gcnt, g_gcnt);
    cudaGetSymbolAddress(&p_w1f, g_W1f);
    cudaGetSymbolAddress(&p_w2f, g_W2f);
    cudaGetSymbolAddress(&p_wu1f, g_WU1f);
    cudaGetSymbolAddress(&p_wu2f, g_WU2f);
    float* h    = (float*)p_h;
    float* agg  = (float*)p_agg;
    float* ef   = (float*)p_ef;
    float* gsum = (float*)p_gsum;
    float* gcnt = (float*)p_gcnt;
    unsigned int* W1f  = (unsigned int*)p_w1f;
    unsigned int* W2f  = (unsigned int*)p_w2f;
    unsigned int* WU1f = (unsigned int*)p_wu1f;
    unsigned int* WU2f = (unsigned int*)p_wu2f;

    cudaFuncSetAttribute(msg_mma_k, cudaFuncAttributeMaxDynamicSharedMemorySize, SMEM_MSG);
    cudaFuncSetAttribute(upd_mma_k, cudaFuncAttributeMaxDynamicSharedMemorySize, SMEM_UPD);

    prep1_k<<<(NL * KC1H * 16 * 32 * 4 + 255) / 256, 256>>>(msg_W1, W1f);
    prep2_k<<<(NL * KC2H * 8 * 32 * 4 + 255) / 256, 256>>>(msg_W2, W2f);
    prepU1_k<<<(NL * 16 * 16 * 32 * 4 + 255) / 256, 256>>>(upd_W1, WU1f);
    prepU2_k<<<(NL * 16 * 8 * 32 * 4 + 255) / 256, 256>>>(upd_W2, WU2f);
    embed_k<<<NN / 16, 128>>>(nf, emb_W1, emb_b1, emb_W2, emb_b2, h);
    rbf_k<<<EE / 256, 256>>>(pos, EI, ef);

    for (int l = 0; l < NL; l++) {
        cudaMemsetAsync(agg, 0, (size_t)NN * DD * sizeof(float), 0);
        msg_mma_k<<<EE / 128, 512, SMEM_MSG>>>(
            EI, h, ef,
            W1f + (size_t)l * KC1H * 16 * 32 * 4,
            msg_b1 + (size_t)l * HH,
            W2f + (size_t)l * KC2H * 8 * 32 * 4,
            msg_b2 + (size_t)l * DD,
            agg);
        upd_mma_k<<<NN / 128, 512, SMEM_UPD>>>(
            h, agg,
            WU1f + (size_t)l * 16 * 16 * 32 * 4,
            upd_b1 + (size_t)l * HH,
            WU2f + (size_t)l * 16 * 8 * 32 * 4,
            upd_b2 + (size_t)l * DD);
    }

    cudaMemsetAsync(gsum, 0, (size_t)BB * DD * sizeof(float), 0);
    cudaMemsetAsync(gcnt, 0, (size_t)BB * sizeof(float), 0);
    cnt_k<<<NN / 256, 256>>>(batch, gcnt);
    gsum_k<<<NN / 32, 128>>>(h, batch, gsum);
    final_k<<<1, 256>>>(gsum, gcnt, r_W1, r_b1, r_W2, r_b2, out);
}